// round 5
// baseline (speedup 1.0000x reference)
#include <cuda_runtime.h>
#include <cuda_bf16.h>
#include <mma.h>
#include <math.h>
#include <stdint.h>

using namespace nvcuda;

// ---------------- problem constants ----------------
#define N_NODESC 50000
#define NVC      50001
#define NPAD     50048             // 391*128, padded rows for boundless GEMM
#define VN       N_NODESC
#define NEC      400000
#define IN_DIMC  256
#define HIDC     128
#define DHIDC    256
#define OUT_DIMC 64
#define NB_SCAN  98
#define VROWS    391
#define MTILES   391

// ---------------- scratch ----------------
__device__ __align__(16) float d_H   [(size_t)NPAD * DHIDC];
__device__ __align__(16) float d_Feat[(size_t)NVC * HIDC];
__device__ __align__(16) __nv_bfloat16 d_Ahi[(size_t)NPAD * IN_DIMC];
__device__ __align__(16) __nv_bfloat16 d_Alo[(size_t)NPAD * IN_DIMC];
__device__ __align__(16) __nv_bfloat16 d_Bhi[DHIDC * IN_DIMC];
__device__ __align__(16) __nv_bfloat16 d_Blo[DHIDC * IN_DIMC];
__device__ float d_As[NVC * 2];
__device__ float d_Ad[NVC * 2];
__device__ int   d_cnt   [N_NODESC];
__device__ int   d_rowptr[N_NODESC + 1];
__device__ int   d_cursor[N_NODESC];
__device__ int   d_csr   [NEC];
__device__ int   d_bsumex[NB_SCAN + 1];
__device__ float d_vacc[IN_DIMC];
__device__ unsigned d_vmax[2];
__device__ float d_vden[2];
__device__ float d_vagg[DHIDC];

// ---------------- helpers ----------------
__device__ __forceinline__ unsigned fenc(float f) {
    unsigned u = __float_as_uint(f);
    return (u & 0x80000000u) ? ~u : (u | 0x80000000u);
}
__device__ __forceinline__ float fdec(unsigned u) {
    return (u & 0x80000000u) ? __uint_as_float(u ^ 0x80000000u)
                             : __uint_as_float(~u);
}
#define ENC_NEG_INF 0x007FFFFFu

__device__ __forceinline__ float lrelu(float v) { return v > 0.f ? v : 0.2f * v; }
__device__ __forceinline__ float wsum(float v) {
#pragma unroll
    for (int o = 16; o; o >>= 1) v += __shfl_xor_sync(0xffffffffu, v, o);
    return v;
}
__device__ __forceinline__ float wmax(float v) {
#pragma unroll
    for (int o = 16; o; o >>= 1) v = fmaxf(v, __shfl_xor_sync(0xffffffffu, v, o));
    return v;
}
__device__ __forceinline__ void ffma2(unsigned long long& d, unsigned long long a,
                                      unsigned long long b) {
    asm("fma.rn.f32x2 %0, %1, %2, %0;" : "+l"(d) : "l"(a), "l"(b));
}
__device__ __forceinline__ float lo32(unsigned long long v) { return __uint_as_float((unsigned)v); }
__device__ __forceinline__ float hi32(unsigned long long v) { return __uint_as_float((unsigned)(v >> 32)); }

__device__ __forceinline__ void split2(float a, float b, unsigned& hi, unsigned& lo) {
    __nv_bfloat16 ha = __float2bfloat16(a), hb = __float2bfloat16(b);
    __nv_bfloat16 la = __float2bfloat16(a - __bfloat162float(ha));
    __nv_bfloat16 lb = __float2bfloat16(b - __bfloat162float(hb));
    __nv_bfloat162 H = {ha, hb}, L = {la, lb};
    hi = *(unsigned*)&H;  lo = *(unsigned*)&L;
}

// ---------------- vnode input mean ----------------
__global__ void vacc_zero_k() { d_vacc[threadIdx.x] = 0.f; }
__global__ void vnode_partial_k(const float* __restrict__ X) {
    int t = threadIdx.x;
    float loc = 0.f;
    for (int r = blockIdx.x; r < N_NODESC; r += gridDim.x)
        loc += X[(size_t)r * IN_DIMC + t];
    atomicAdd(&d_vacc[t], loc);
}

// ---------------- conversions ----------------
__global__ void convx0_k(const float* __restrict__ X) {
    size_t i4 = (size_t)blockIdx.x * blockDim.x + threadIdx.x;
    if (i4 >= (size_t)NVC * IN_DIMC / 4) return;
    size_t i = i4 * 4;
    int row = (int)(i / IN_DIMC);
    int k   = (int)(i % IN_DIMC);
    float4 v;
    if (row < N_NODESC) v = *(const float4*)&X[i];
    else {
        const float inv = 1.f / (float)N_NODESC;
        v.x = d_vacc[k] * inv; v.y = d_vacc[k + 1] * inv;
        v.z = d_vacc[k + 2] * inv; v.w = d_vacc[k + 3] * inv;
    }
    uint2 hi, lo;
    split2(v.x, v.y, hi.x, lo.x);
    split2(v.z, v.w, hi.y, lo.y);
    *(uint2*)&d_Ahi[i] = hi;
    *(uint2*)&d_Alo[i] = lo;
}
__global__ void convw_k(const float* __restrict__ W, int K) {
    int idx = blockIdx.x * blockDim.x + threadIdx.x;  // n-major, k fastest
    if (idx >= DHIDC * K) return;
    int n = idx / K, k = idx % K;
    float v = W[(size_t)k * DHIDC + n];
    __nv_bfloat16 h = __float2bfloat16(v);
    d_Bhi[idx] = h;
    d_Blo[idx] = __float2bfloat16(v - __bfloat162float(h));
}

// ---------------- CSR build ----------------
__global__ void hist_k(const int* __restrict__ ei) {
    int e = blockIdx.x * blockDim.x + threadIdx.x;
    if (e < NEC) atomicAdd(&d_cnt[ei[NEC + e]], 1);
}
__global__ void scanb_k() {
    __shared__ int bs[NB_SCAN];
    int b = threadIdx.x;
    if (b < NB_SCAN) {
        int s = 0;
        int base = b * 512;
#pragma unroll 8
        for (int i = 0; i < 512; i++) {
            int idx = base + i;
            if (idx < N_NODESC) s += d_cnt[idx];
        }
        bs[b] = s;
    }
    __syncthreads();
    if (threadIdx.x == 0) {
        int carry = 0;
        for (int i = 0; i < NB_SCAN; i++) { d_bsumex[i] = carry; carry += bs[i]; }
        d_bsumex[NB_SCAN] = carry;
    }
}
__global__ void rowptr_k() {
    __shared__ int sh[512];
    int t = threadIdx.x;
    int idx = blockIdx.x * 512 + t;
    int c = (idx < N_NODESC) ? d_cnt[idx] : 0;
    sh[t] = c;
    __syncthreads();
#pragma unroll
    for (int o = 1; o < 512; o <<= 1) {
        int v = (t >= o) ? sh[t - o] : 0;
        __syncthreads();
        sh[t] += v;
        __syncthreads();
    }
    if (idx < N_NODESC) {
        int p = d_bsumex[blockIdx.x] + sh[t] - c;
        d_rowptr[idx] = p;
        d_cursor[idx] = p;
    }
    if (idx == 0) d_rowptr[N_NODESC] = NEC;
}
__global__ void scatter_k(const int* __restrict__ ei) {
    int e = blockIdx.x * blockDim.x + threadIdx.x;
    if (e >= NEC) return;
    int d = ei[NEC + e];
    int p = atomicAdd(&d_cursor[d], 1);
    d_csr[p] = ei[e];
}

// ---------------- wmma bf16 hi/lo GEMM: d_H = A @ B^T ----------------
// block 128(M) x 128(N), 8 warps (4 m-groups x 2 n-groups), warp tile 32x64
#define SSTR 48    // smem k-stride (elements): 96B rows, 32B-aligned fragments
__global__ void __launch_bounds__(256) wgemm_k(int K) {
    __shared__ __align__(32) __nv_bfloat16 Ah[128][SSTR];
    __shared__ __align__(32) __nv_bfloat16 Al[128][SSTR];
    __shared__ __align__(32) __nv_bfloat16 Bh[128][SSTR];
    __shared__ __align__(32) __nv_bfloat16 Bl[128][SSTR];

    const int tid = threadIdx.x;
    const int wid = tid >> 5;
    const int wm = wid & 3;          // 0..3 -> 32-row band
    const int wn = wid >> 2;         // 0..1 -> 64-col band
    const int row0 = blockIdx.y * 128;
    const int col0 = blockIdx.x * 128;

    wmma::fragment<wmma::accumulator, 16, 16, 16, float> acc[2][4];
#pragma unroll
    for (int i = 0; i < 2; i++)
#pragma unroll
        for (int j = 0; j < 4; j++) wmma::fill_fragment(acc[i][j], 0.f);

    const int nch = K >> 5;          // chunks of 32
    for (int c = 0; c < nch; c++) {
        const int k0 = c << 5;
        __syncthreads();
#pragma unroll
        for (int s = tid; s < 512; s += 256) {
            int r = s >> 2, q = s & 3;
            *(uint4*)&Ah[r][q * 8] = *(const uint4*)&d_Ahi[(size_t)(row0 + r) * K + k0 + q * 8];
            *(uint4*)&Al[r][q * 8] = *(const uint4*)&d_Alo[(size_t)(row0 + r) * K + k0 + q * 8];
            *(uint4*)&Bh[r][q * 8] = *(const uint4*)&d_Bhi[(size_t)(col0 + r) * K + k0 + q * 8];
            *(uint4*)&Bl[r][q * 8] = *(const uint4*)&d_Blo[(size_t)(col0 + r) * K + k0 + q * 8];
        }
        __syncthreads();

#pragma unroll
        for (int kk = 0; kk < 32; kk += 16) {
            wmma::fragment<wmma::matrix_a, 16, 16, 16, __nv_bfloat16, wmma::row_major> ah[2], al[2];
#pragma unroll
            for (int i = 0; i < 2; i++) {
                wmma::load_matrix_sync(ah[i], &Ah[wm * 32 + i * 16][kk], SSTR);
                wmma::load_matrix_sync(al[i], &Al[wm * 32 + i * 16][kk], SSTR);
            }
#pragma unroll
            for (int j = 0; j < 4; j++) {
                wmma::fragment<wmma::matrix_b, 16, 16, 16, __nv_bfloat16, wmma::col_major> bh, bl;
                wmma::load_matrix_sync(bh, &Bh[wn * 64 + j * 16][kk], SSTR);
                wmma::load_matrix_sync(bl, &Bl[wn * 64 + j * 16][kk], SSTR);
#pragma unroll
                for (int i = 0; i < 2; i++) {
                    wmma::mma_sync(acc[i][j], ah[i], bh, acc[i][j]);
                    wmma::mma_sync(acc[i][j], ah[i], bl, acc[i][j]);
                    wmma::mma_sync(acc[i][j], al[i], bh, acc[i][j]);
                }
            }
        }
    }
#pragma unroll
    for (int i = 0; i < 2; i++)
#pragma unroll
        for (int j = 0; j < 4; j++)
            wmma::store_matrix_sync(
                &d_H[(size_t)(row0 + wm * 32 + i * 16) * DHIDC + col0 + wn * 64 + j * 16],
                acc[i][j], DHIDC, wmma::mem_row_major);
}

// ---------------- attention logits per node ----------------
__global__ void alpha_k(const float* __restrict__ asrc,
                        const float* __restrict__ adst) {
    int n = blockIdx.x, t = threadIdx.x;           // 256 threads
    float hv = d_H[(size_t)n * DHIDC + t];
    __shared__ float ss[DHIDC], sd[DHIDC];
    ss[t] = hv * asrc[t];
    sd[t] = hv * adst[t];
    __syncthreads();
    for (int off = 64; off >= 1; off >>= 1) {
        if ((t & 127) < off) { ss[t] += ss[t + off]; sd[t] += sd[t + off]; }
        __syncthreads();
    }
    if ((t & 127) == 0) {
        int head = t >> 7;
        d_As[n * 2 + head] = ss[t];
        d_Ad[n * 2 + head] = sd[t];
    }
}

// ---------------- fp32 f32x2 GEMM (final projection only) ----------------
template<int BN>
__global__ void sgemm_k(const float* __restrict__ A, const float* __restrict__ B,
                        const float* __restrict__ bias, float* __restrict__ C,
                        int M, int K, int N) {
    constexpr int BM = 128, BK = 16, TPB = 2 * BN, GRP = BN / 8;
    __shared__ __align__(16) float2 As2[BK][BM];
    __shared__ __align__(16) float  Bs [BK][BN];
    const int tid = threadIdx.x;
    const int tn = tid % GRP, tm = tid / GRP;
    const int row0 = blockIdx.y * BM, col0 = blockIdx.x * BN;
    unsigned long long acc[8][4];
#pragma unroll
    for (int i = 0; i < 8; i++)
#pragma unroll
        for (int j = 0; j < 4; j++) acc[i][j] = 0ull;
    for (int k0 = 0; k0 < K; k0 += BK) {
        __syncthreads();
#pragma unroll
        for (int s = tid; s < BM * 4; s += TPB) {
            int r = s >> 2, q = s & 3;
            int row = row0 + r;
            float4 v = (row < M) ? *(const float4*)&A[(size_t)row * K + k0 + q * 4]
                                 : make_float4(0.f, 0.f, 0.f, 0.f);
            As2[q * 4 + 0][r] = make_float2(v.x, v.x);
            As2[q * 4 + 1][r] = make_float2(v.y, v.y);
            As2[q * 4 + 2][r] = make_float2(v.z, v.z);
            As2[q * 4 + 3][r] = make_float2(v.w, v.w);
        }
#pragma unroll
        for (int s = tid; s < BK * BN / 4; s += TPB) {
            int br = s / (BN / 4), bc = s % (BN / 4);
            *(float4*)&Bs[br][bc * 4] =
                *(const float4*)&B[(size_t)(k0 + br) * N + col0 + bc * 4];
        }
        __syncthreads();
#pragma unroll
        for (int kk = 0; kk < BK; kk++) {
            unsigned long long a[8], b[4];
            const ulonglong2* ap = (const ulonglong2*)&As2[kk][tm * 8];
            ulonglong2 a01 = ap[0], a23 = ap[1], a45 = ap[2], a67 = ap[3];
            a[0] = a01.x; a[1] = a01.y; a[2] = a23.x; a[3] = a23.y;
            a[4] = a45.x; a[5] = a45.y; a[6] = a67.x; a[7] = a67.y;
            const ulonglong2* bp = (const ulonglong2*)&Bs[kk][tn * 8];
            ulonglong2 b01 = bp[0], b23 = bp[1];
            b[0] = b01.x; b[1] = b01.y; b[2] = b23.x; b[3] = b23.y;
#pragma unroll
            for (int i = 0; i < 8; i++)
#pragma unroll
                for (int j = 0; j < 4; j++) ffma2(acc[i][j], a[i], b[j]);
        }
    }
    float bv[8];
#pragma unroll
    for (int j = 0; j < 8; j++) bv[j] = bias ? bias[col0 + tn * 8 + j] : 0.f;
#pragma unroll
    for (int i = 0; i < 8; i++) {
        int row = row0 + tm * 8 + i;
        if (row < M) {
            float4 o0, o1;
            o0.x = lo32(acc[i][0]) + bv[0]; o0.y = hi32(acc[i][0]) + bv[1];
            o0.z = lo32(acc[i][1]) + bv[2]; o0.w = hi32(acc[i][1]) + bv[3];
            o1.x = lo32(acc[i][2]) + bv[4]; o1.y = hi32(acc[i][2]) + bv[5];
            o1.z = lo32(acc[i][3]) + bv[6]; o1.w = hi32(acc[i][3]) + bv[7];
            *(float4*)&C[(size_t)row * N + col0 + tn * 8]     = o0;
            *(float4*)&C[(size_t)row * N + col0 + tn * 8 + 4] = o1;
        }
    }
}

// ---------------- vnode destination ----------------
__global__ void vn_init_k() {
    int t = threadIdx.x;
    d_vagg[t] = 0.f;
    if (t < 2) { d_vmax[t] = ENC_NEG_INF; d_vden[t] = 0.f; }
}
__global__ void vn_max_k() {
    int idx = blockIdx.x * 512 + threadIdx.x;
    float Ad0 = d_Ad[2 * VN], Ad1 = d_Ad[2 * VN + 1];
    float m0 = -INFINITY, m1 = -INFINITY;
    if (idx < NVC) {
        m0 = lrelu(d_As[2 * idx] + Ad0);
        m1 = lrelu(d_As[2 * idx + 1] + Ad1);
    }
    __shared__ float s0[512], s1[512];
    int t = threadIdx.x;
    s0[t] = m0; s1[t] = m1;
    __syncthreads();
    for (int o = 256; o; o >>= 1) {
        if (t < o) { s0[t] = fmaxf(s0[t], s0[t + o]); s1[t] = fmaxf(s1[t], s1[t + o]); }
        __syncthreads();
    }
    if (t == 0) { atomicMax(&d_vmax[0], fenc(s0[0])); atomicMax(&d_vmax[1], fenc(s1[0])); }
}
__global__ void vn_den_k() {
    int idx = blockIdx.x * 512 + threadIdx.x;
    float Ad0 = d_Ad[2 * VN], Ad1 = d_Ad[2 * VN + 1];
    float m0 = fdec(d_vmax[0]), m1 = fdec(d_vmax[1]);
    float e0 = 0.f, e1 = 0.f;
    if (idx < NVC) {
        e0 = expf(lrelu(d_As[2 * idx] + Ad0) - m0);
        e1 = expf(lrelu(d_As[2 * idx + 1] + Ad1) - m1);
    }
    __shared__ float s0[512], s1[512];
    int t = threadIdx.x;
    s0[t] = e0; s1[t] = e1;
    __syncthreads();
    for (int o = 256; o; o >>= 1) {
        if (t < o) { s0[t] += s0[t + o]; s1[t] += s1[t + o]; }
        __syncthreads();
    }
    if (t == 0) { atomicAdd(&d_vden[0], s0[0]); atomicAdd(&d_vden[1], s1[0]); }
}
__global__ void vn_agg_k() {
    int t = threadIdx.x;
    int r0 = blockIdx.x * VROWS;
    int r1 = min(r0 + VROWS, NVC);
    float Ad0 = d_Ad[2 * VN], Ad1 = d_Ad[2 * VN + 1];
    float m0 = fdec(d_vmax[0]), m1 = fdec(d_vmax[1]);
    __shared__ float w0sh[256], w1sh[256];
    float acc = 0.f;
    int head = t >> 7;
    for (int base = r0; base < r1; base += 256) {
        int r = base + t;
        if (r < r1) {
            w0sh[t] = expf(lrelu(d_As[2 * r] + Ad0) - m0);
            w1sh[t] = expf(lrelu(d_As[2 * r + 1] + Ad1) - m1);
        }
        __syncthreads();
        int cnt = min(256, r1 - base);
        const float* wsh = head ? w1sh : w0sh;
        for (int j = 0; j < cnt; j++)
            acc += wsh[j] * d_H[(size_t)(base + j) * DHIDC + t];
        __syncthreads();
    }
    atomicAdd(&d_vagg[t], acc);
}
__global__ void vn_fin_k(const float* __restrict__ b, const float* __restrict__ g,
                         const float* __restrict__ be) {
    int t = threadIdx.x;
    float den0 = d_vden[0] + 1e-16f, den1 = d_vden[1] + 1e-16f;
    float v = 0.5f * (d_vagg[t] / den0 + d_vagg[HIDC + t] / den1) + b[t];
    __shared__ float sh[HIDC];
    sh[t] = v; __syncthreads();
    for (int o = 64; o; o >>= 1) { if (t < o) sh[t] += sh[t + o]; __syncthreads(); }
    float mu = sh[0] * (1.f / HIDC);
    __syncthreads();
    float dv = v - mu;
    sh[t] = dv * dv; __syncthreads();
    for (int o = 64; o; o >>= 1) { if (t < o) sh[t] += sh[t + o]; __syncthreads(); }
    float var = sh[0] * (1.f / HIDC);
    float y = dv * rsqrtf(var + 1e-5f) * g[t] + be[t];
    float ge = 0.5f * y * (1.f + erff(y * 0.70710678118654752f));
    d_Feat[(size_t)VN * HIDC + t] = ge;
    __nv_bfloat16 h = __float2bfloat16(ge);
    d_Ahi[(size_t)VN * HIDC + t] = h;
    d_Alo[(size_t)VN * HIDC + t] = __float2bfloat16(ge - __bfloat162float(h));
}

// ---------------- fused per-node softmax+aggregate+bias+LN+GELU (+ bf16 split out) ----------------
__global__ void node_k(const float* __restrict__ b, const float* __restrict__ g,
                       const float* __restrict__ be) {
    int gid  = blockIdx.x * blockDim.x + threadIdx.x;
    int d    = gid >> 5;
    int lane = gid & 31;
    if (d >= N_NODESC) return;
    float Ad0 = d_Ad[2 * d], Ad1 = d_Ad[2 * d + 1];
    int off = d_rowptr[d], end = d_rowptr[d + 1];

    float ev0 = lrelu(d_As[2 * VN] + Ad0), ev1 = lrelu(d_As[2 * VN + 1] + Ad1);
    float es0 = lrelu(d_As[2 * d]  + Ad0), es1 = lrelu(d_As[2 * d + 1]  + Ad1);

    float m0 = fmaxf(ev0, es0), m1 = fmaxf(ev1, es1);
    for (int i = off + lane; i < end; i += 32) {
        int s = d_csr[i];
        m0 = fmaxf(m0, lrelu(d_As[2 * s]     + Ad0));
        m1 = fmaxf(m1, lrelu(d_As[2 * s + 1] + Ad1));
    }
    m0 = wmax(m0); m1 = wmax(m1);

    float den0 = 0.f, den1 = 0.f;
    for (int i = off + lane; i < end; i += 32) {
        int s = d_csr[i];
        den0 += expf(lrelu(d_As[2 * s]     + Ad0) - m0);
        den1 += expf(lrelu(d_As[2 * s + 1] + Ad1) - m1);
    }
    den0 = wsum(den0) + expf(ev0 - m0) + expf(es0 - m0);
    den1 = wsum(den1) + expf(ev1 - m1) + expf(es1 - m1);
    float inv0 = 0.5f / (den0 + 1e-16f);
    float inv1 = 0.5f / (den1 + 1e-16f);

    float ax = 0.f, ay = 0.f, az = 0.f, aw = 0.f;
    const int c = lane * 4;
    for (int j = off; j < end; j++) {
        int s = d_csr[j];
        float w0 = expf(lrelu(d_As[2 * s]     + Ad0) - m0) * inv0;
        float w1 = expf(lrelu(d_As[2 * s + 1] + Ad1) - m1) * inv1;
        float4 v0 = *(const float4*)&d_H[(size_t)s * DHIDC + c];
        float4 v1 = *(const float4*)&d_H[(size_t)s * DHIDC + HIDC + c];
        ax += w0 * v0.x + w1 * v1.x;
        ay += w0 * v0.y + w1 * v1.y;
        az += w0 * v0.z + w1 * v1.z;
        aw += w0 * v0.w + w1 * v1.w;
    }
    {
        float w0 = expf(ev0 - m0) * inv0, w1 = expf(ev1 - m1) * inv1;
        float4 v0 = *(const float4*)&d_H[(size_t)VN * DHIDC + c];
        float4 v1 = *(const float4*)&d_H[(size_t)VN * DHIDC + HIDC + c];
        ax += w0 * v0.x + w1 * v1.x; ay += w0 * v0.y + w1 * v1.y;
        az += w0 * v0.z + w1 * v1.z; aw += w0 * v0.w + w1 * v1.w;
    }
    {
        float w0 = expf(es0 - m0) * inv0, w1 = expf(es1 - m1) * inv1;
        float4 v0 = *(const float4*)&d_H[(size_t)d * DHIDC + c];
        float4 v1 = *(const float4*)&d_H[(size_t)d * DHIDC + HIDC + c];
        ax += w0 * v0.x + w1 * v1.x; ay += w0 * v0.y + w1 * v1.y;
        az += w0 * v0.z + w1 * v1.z; aw += w0 * v0.w + w1 * v1.w;
    }

    float y0 = ax + b[c], y1 = ay + b[c + 1], y2 = az + b[c + 2], y3 = aw + b[c + 3];
    float mu = wsum(y0 + y1 + y2 + y3) * (1.f / HIDC);
    float d0 = y0 - mu, d1 = y1 - mu, d2 = y2 - mu, d3 = y3 - mu;
    float var = wsum(d0 * d0 + d1 * d1 + d2 * d2 + d3 * d3) * (1.f / HIDC);
    float rs = rsqrtf(var + 1e-5f);
    float z0 = d0 * rs * g[c]     + be[c];
    float z1 = d1 * rs * g[c + 1] + be[c + 1];
    float z2 = d2 * rs * g[c + 2] + be[c + 2];
    float z3 = d3 * rs * g[c + 3] + be[c + 3];
    const float kk = 0.70710678118654752f;
    float4 o;
    o.x = 0.5f * z0 * (1.f + erff(z0 * kk));
    o.y = 0.5f * z1 * (1.f + erff(z1 * kk));
    o.z = 0.5f * z2 * (1.f + erff(z2 * kk));
    o.w = 0.5f * z3 * (1.f + erff(z3 * kk));
    *(float4*)&d_Feat[(size_t)d * HIDC + c] = o;
    uint2 hi, lo;
    split2(o.x, o.y, hi.x, lo.x);
    split2(o.z, o.w, hi.y, lo.y);
    *(uint2*)&d_Ahi[(size_t)d * HIDC + c] = hi;
    *(uint2*)&d_Alo[(size_t)d * HIDC + c] = lo;
}

// ---------------- host launch ----------------
extern "C" void kernel_launch(void* const* d_in, const int* in_sizes, int n_in,
                              void* d_out, int out_size) {
    (void)in_sizes; (void)n_in; (void)out_size;
    const float* X  = (const float*)d_in[0];
    const int*   ei = (const int*)  d_in[1];
    const float* W[3]  = {(const float*)d_in[3],  (const float*)d_in[9],  (const float*)d_in[15]};
    const float* aS[3] = {(const float*)d_in[4],  (const float*)d_in[10], (const float*)d_in[16]};
    const float* aD[3] = {(const float*)d_in[5],  (const float*)d_in[11], (const float*)d_in[17]};
    const float* bb[3] = {(const float*)d_in[6],  (const float*)d_in[12], (const float*)d_in[18]};
    const float* gg[3] = {(const float*)d_in[7],  (const float*)d_in[13], (const float*)d_in[19]};
    const float* bE[3] = {(const float*)d_in[8],  (const float*)d_in[14], (const float*)d_in[20]};
    const float* Wout  = (const float*)d_in[21];
    const float* bout  = (const float*)d_in[22];
    float* out = (float*)d_out;

    float* dFeat; cudaGetSymbolAddress((void**)&dFeat, d_Feat);
    int* dCnt;    cudaGetSymbolAddress((void**)&dCnt, d_cnt);

    // vnode mean + bf16 split of layer0 input
    vacc_zero_k<<<1, IN_DIMC>>>();
    vnode_partial_k<<<512, IN_DIMC>>>(X);
    convx0_k<<<(int)(((size_t)NVC * IN_DIMC / 4 + 255) / 256), 256>>>(X);

    // CSR
    cudaMemsetAsync(dCnt, 0, N_NODESC * sizeof(int), 0);
    const int eb = (NEC + 255) / 256;
    hist_k<<<eb, 256>>>(ei);
    scanb_k<<<1, 128>>>();
    rowptr_k<<<NB_SCAN, 512>>>();
    scatter_k<<<eb, 256>>>(ei);

    const int node_blocks = (N_NODESC * 32 + 255) / 256;

    for (int l = 0; l < 3; l++) {
        int K = (l == 0) ? IN_DIMC : HIDC;
        convw_k<<<(DHIDC * K + 255) / 256, 256>>>(W[l], K);
        dim3 grid(DHIDC / 128, MTILES);
        wgemm_k<<<grid, 256>>>(K);
        alpha_k<<<NVC, DHIDC>>>(aS[l], aD[l]);
        vn_init_k<<<1, DHIDC>>>();
        vn_max_k<<<NB_SCAN, 512>>>();
        vn_den_k<<<NB_SCAN, 512>>>();
        vn_agg_k<<<128, 256>>>();
        vn_fin_k<<<1, HIDC>>>(bb[l], gg[l], bE[l]);
        node_k<<<node_blocks, 256>>>(bb[l], gg[l], bE[l]);
    }

    dim3 gridF(1, (N_NODESC + 127) / 128);
    sgemm_k<64><<<gridF, 128>>>(dFeat, Wout, bout, out, N_NODESC, HIDC, OUT_DIMC);
}

// round 6
// speedup vs baseline: 1.1082x; 1.1082x over previous
#include <cuda_runtime.h>
#include <cuda_bf16.h>
#include <mma.h>
#include <math.h>
#include <stdint.h>

using namespace nvcuda;

// ---------------- problem constants ----------------
#define N_NODESC 50000
#define NVC      50001
#define NPAD     50048
#define VN       N_NODESC
#define NEC      400000
#define IN_DIMC  256
#define HIDC     128
#define DHIDC    256
#define OUT_DIMC 64
#define NB_SCAN  98
#define VROWS    391
#define MTILES   391
#define VAGG_B   128

// ---------------- scratch ----------------
__device__ __align__(16) float d_H   [(size_t)NPAD * DHIDC];
__device__ __align__(16) float d_Feat[(size_t)NVC * HIDC];
__device__ __align__(16) __nv_bfloat16 d_Ahi[(size_t)NPAD * IN_DIMC];
__device__ __align__(16) __nv_bfloat16 d_Alo[(size_t)NPAD * IN_DIMC];
__device__ __align__(16) __nv_bfloat16 d_Bhi[3][DHIDC * IN_DIMC];
__device__ __align__(16) __nv_bfloat16 d_Blo[3][DHIDC * IN_DIMC];
__device__ float d_As[NVC * 2];
__device__ float d_Ad[NVC * 2];
__device__ int   d_cnt   [N_NODESC];
__device__ int   d_rowptr[N_NODESC + 1];
__device__ int   d_cursor[N_NODESC];
__device__ int   d_csr   [NEC];
__device__ int   d_bsumex[NB_SCAN + 1];
__device__ float d_vacc[IN_DIMC];
__device__ float d_vmaxf[2];
__device__ float d_vdenf[2];
__device__ float d_vaggp[VAGG_B][DHIDC];

// ---------------- helpers ----------------
__device__ __forceinline__ float lrelu(float v) { return v > 0.f ? v : 0.2f * v; }
__device__ __forceinline__ float wsum(float v) {
#pragma unroll
    for (int o = 16; o; o >>= 1) v += __shfl_xor_sync(0xffffffffu, v, o);
    return v;
}
__device__ __forceinline__ float wmax(float v) {
#pragma unroll
    for (int o = 16; o; o >>= 1) v = fmaxf(v, __shfl_xor_sync(0xffffffffu, v, o));
    return v;
}
__device__ __forceinline__ void ffma2(unsigned long long& d, unsigned long long a,
                                      unsigned long long b) {
    asm("fma.rn.f32x2 %0, %1, %2, %0;" : "+l"(d) : "l"(a), "l"(b));
}
__device__ __forceinline__ float lo32(unsigned long long v) { return __uint_as_float((unsigned)v); }
__device__ __forceinline__ float hi32(unsigned long long v) { return __uint_as_float((unsigned)(v >> 32)); }

__device__ __forceinline__ void split2(float a, float b, unsigned& hi, unsigned& lo) {
    __nv_bfloat16 ha = __float2bfloat16(a), hb = __float2bfloat16(b);
    __nv_bfloat16 la = __float2bfloat16(a - __bfloat162float(ha));
    __nv_bfloat16 lb = __float2bfloat16(b - __bfloat162float(hb));
    __nv_bfloat162 H = {ha, hb}, L = {la, lb};
    hi = *(unsigned*)&H;  lo = *(unsigned*)&L;
}

// ---------------- vnode input mean ----------------
__global__ void vacc_zero_k() { d_vacc[threadIdx.x] = 0.f; }
__global__ void vnode_partial_k(const float* __restrict__ X) {
    int t = threadIdx.x;
    float loc = 0.f;
    for (int r = blockIdx.x; r < N_NODESC; r += gridDim.x)
        loc += X[(size_t)r * IN_DIMC + t];
    atomicAdd(&d_vacc[t], loc);
}

// ---------------- conversions ----------------
__global__ void convx0_k(const float* __restrict__ X) {
    size_t i4 = (size_t)blockIdx.x * blockDim.x + threadIdx.x;
    if (i4 >= (size_t)NVC * IN_DIMC / 4) return;
    size_t i = i4 * 4;
    int row = (int)(i / IN_DIMC);
    int k   = (int)(i % IN_DIMC);
    float4 v;
    if (row < N_NODESC) v = *(const float4*)&X[i];
    else {
        const float inv = 1.f / (float)N_NODESC;
        v.x = d_vacc[k] * inv; v.y = d_vacc[k + 1] * inv;
        v.z = d_vacc[k + 2] * inv; v.w = d_vacc[k + 3] * inv;
    }
    uint2 hi, lo;
    split2(v.x, v.y, hi.x, lo.x);
    split2(v.z, v.w, hi.y, lo.y);
    *(uint2*)&d_Ahi[i] = hi;
    *(uint2*)&d_Alo[i] = lo;
}
// all three layers' weights in one launch; n-major (k fastest)
__global__ void convw_all_k(const float* __restrict__ W0, const float* __restrict__ W1,
                            const float* __restrict__ W2) {
    int idx = blockIdx.x * blockDim.x + threadIdx.x;
    int l, K; const float* W; int base = idx;
    if (base < DHIDC * IN_DIMC)      { l = 0; K = IN_DIMC; W = W0; }
    else if ((base -= DHIDC * IN_DIMC) < DHIDC * HIDC) { l = 1; K = HIDC; W = W1; }
    else if ((base -= DHIDC * HIDC) < DHIDC * HIDC)    { l = 2; K = HIDC; W = W2; }
    else return;
    int n = base / K, k = base % K;
    float v = W[(size_t)k * DHIDC + n];
    __nv_bfloat16 h = __float2bfloat16(v);
    d_Bhi[l][n * K + k] = h;
    d_Blo[l][n * K + k] = __float2bfloat16(v - __bfloat162float(h));
}

// ---------------- CSR build ----------------
__global__ void hist_k(const int* __restrict__ ei) {
    int e = blockIdx.x * blockDim.x + threadIdx.x;
    if (e < NEC) atomicAdd(&d_cnt[ei[NEC + e]], 1);
}
__global__ void scanb_k() {
    __shared__ int bs[NB_SCAN];
    int b = threadIdx.x;
    if (b < NB_SCAN) {
        int s = 0;
        int base = b * 512;
#pragma unroll 8
        for (int i = 0; i < 512; i++) {
            int idx = base + i;
            if (idx < N_NODESC) s += d_cnt[idx];
        }
        bs[b] = s;
    }
    __syncthreads();
    if (threadIdx.x == 0) {
        int carry = 0;
        for (int i = 0; i < NB_SCAN; i++) { d_bsumex[i] = carry; carry += bs[i]; }
        d_bsumex[NB_SCAN] = carry;
    }
}
__global__ void rowptr_k() {
    __shared__ int sh[512];
    int t = threadIdx.x;
    int idx = blockIdx.x * 512 + t;
    int c = (idx < N_NODESC) ? d_cnt[idx] : 0;
    sh[t] = c;
    __syncthreads();
#pragma unroll
    for (int o = 1; o < 512; o <<= 1) {
        int v = (t >= o) ? sh[t - o] : 0;
        __syncthreads();
        sh[t] += v;
        __syncthreads();
    }
    if (idx < N_NODESC) {
        int p = d_bsumex[blockIdx.x] + sh[t] - c;
        d_rowptr[idx] = p;
        d_cursor[idx] = p;
    }
    if (idx == 0) d_rowptr[N_NODESC] = NEC;
}
__global__ void scatter_k(const int* __restrict__ ei) {
    int e = blockIdx.x * blockDim.x + threadIdx.x;
    if (e >= NEC) return;
    int d = ei[NEC + e];
    int p = atomicAdd(&d_cursor[d], 1);
    d_csr[p] = ei[e];
}

// ---------------- wmma bf16 hi/lo GEMM: d_H = A @ B^T ----------------
#define SSTR 48
__global__ void __launch_bounds__(256) wgemm_k(const __nv_bfloat16* __restrict__ Bhi,
                                               const __nv_bfloat16* __restrict__ Blo,
                                               int K) {
    __shared__ __align__(32) __nv_bfloat16 Ah[128][SSTR];
    __shared__ __align__(32) __nv_bfloat16 Al[128][SSTR];
    __shared__ __align__(32) __nv_bfloat16 Bh[128][SSTR];
    __shared__ __align__(32) __nv_bfloat16 Bl[128][SSTR];

    const int tid = threadIdx.x;
    const int wid = tid >> 5;
    const int wm = wid & 3;
    const int wn = wid >> 2;
    const int row0 = blockIdx.y * 128;
    const int col0 = blockIdx.x * 128;

    wmma::fragment<wmma::accumulator, 16, 16, 16, float> acc[2][4];
#pragma unroll
    for (int i = 0; i < 2; i++)
#pragma unroll
        for (int j = 0; j < 4; j++) wmma::fill_fragment(acc[i][j], 0.f);

    const int nch = K >> 5;
    for (int c = 0; c < nch; c++) {
        const int k0 = c << 5;
        __syncthreads();
#pragma unroll
        for (int s = tid; s < 512; s += 256) {
            int r = s >> 2, q = s & 3;
            *(uint4*)&Ah[r][q * 8] = *(const uint4*)&d_Ahi[(size_t)(row0 + r) * K + k0 + q * 8];
            *(uint4*)&Al[r][q * 8] = *(const uint4*)&d_Alo[(size_t)(row0 + r) * K + k0 + q * 8];
            *(uint4*)&Bh[r][q * 8] = *(const uint4*)&Bhi[(size_t)(col0 + r) * K + k0 + q * 8];
            *(uint4*)&Bl[r][q * 8] = *(const uint4*)&Blo[(size_t)(col0 + r) * K + k0 + q * 8];
        }
        __syncthreads();

#pragma unroll
        for (int kk = 0; kk < 32; kk += 16) {
            wmma::fragment<wmma::matrix_a, 16, 16, 16, __nv_bfloat16, wmma::row_major> ah[2], al[2];
#pragma unroll
            for (int i = 0; i < 2; i++) {
                wmma::load_matrix_sync(ah[i], &Ah[wm * 32 + i * 16][kk], SSTR);
                wmma::load_matrix_sync(al[i], &Al[wm * 32 + i * 16][kk], SSTR);
            }
#pragma unroll
            for (int j = 0; j < 4; j++) {
                wmma::fragment<wmma::matrix_b, 16, 16, 16, __nv_bfloat16, wmma::col_major> bh, bl;
                wmma::load_matrix_sync(bh, &Bh[wn * 64 + j * 16][kk], SSTR);
                wmma::load_matrix_sync(bl, &Bl[wn * 64 + j * 16][kk], SSTR);
#pragma unroll
                for (int i = 0; i < 2; i++) {
                    wmma::mma_sync(acc[i][j], ah[i], bh, acc[i][j]);
                    wmma::mma_sync(acc[i][j], ah[i], bl, acc[i][j]);
                    wmma::mma_sync(acc[i][j], al[i], bh, acc[i][j]);
                }
            }
        }
    }
#pragma unroll
    for (int i = 0; i < 2; i++)
#pragma unroll
        for (int j = 0; j < 4; j++)
            wmma::store_matrix_sync(
                &d_H[(size_t)(row0 + wm * 32 + i * 16) * DHIDC + col0 + wn * 64 + j * 16],
                acc[i][j], DHIDC, wmma::mem_row_major);
}

// ---------------- attention logits: warp per node ----------------
__global__ void alpha_k(const float* __restrict__ asrc,
                        const float* __restrict__ adst) {
    int gid  = blockIdx.x * blockDim.x + threadIdx.x;
    int n    = gid >> 5;
    int lane = gid & 31;
    if (n >= NVC) return;
    const int c = lane * 4;
    float4 h0 = *(const float4*)&d_H[(size_t)n * DHIDC + c];
    float4 h1 = *(const float4*)&d_H[(size_t)n * DHIDC + HIDC + c];
    float4 s0 = *(const float4*)&asrc[c];
    float4 s1 = *(const float4*)&asrc[HIDC + c];
    float4 e0 = *(const float4*)&adst[c];
    float4 e1 = *(const float4*)&adst[HIDC + c];
    float as0 = h0.x * s0.x + h0.y * s0.y + h0.z * s0.z + h0.w * s0.w;
    float as1 = h1.x * s1.x + h1.y * s1.y + h1.z * s1.z + h1.w * s1.w;
    float ad0 = h0.x * e0.x + h0.y * e0.y + h0.z * e0.z + h0.w * e0.w;
    float ad1 = h1.x * e1.x + h1.y * e1.y + h1.z * e1.z + h1.w * e1.w;
    as0 = wsum(as0); as1 = wsum(as1); ad0 = wsum(ad0); ad1 = wsum(ad1);
    if (lane == 0) {
        d_As[2 * n] = as0; d_As[2 * n + 1] = as1;
        d_Ad[2 * n] = ad0; d_Ad[2 * n + 1] = ad1;
    }
}

// ---------------- vnode: fused max + denom (single block) ----------------
__global__ void vn_pre_k() {
    __shared__ float sm0[1024], sm1[1024];
    int t = threadIdx.x;
    float Ad0 = d_Ad[2 * VN], Ad1 = d_Ad[2 * VN + 1];
    float m0 = -INFINITY, m1 = -INFINITY;
    for (int i = t; i < NVC; i += 1024) {
        m0 = fmaxf(m0, lrelu(d_As[2 * i]     + Ad0));
        m1 = fmaxf(m1, lrelu(d_As[2 * i + 1] + Ad1));
    }
    sm0[t] = m0; sm1[t] = m1;
    __syncthreads();
    for (int o = 512; o; o >>= 1) {
        if (t < o) { sm0[t] = fmaxf(sm0[t], sm0[t + o]); sm1[t] = fmaxf(sm1[t], sm1[t + o]); }
        __syncthreads();
    }
    m0 = sm0[0]; m1 = sm1[0];
    __syncthreads();
    float s0 = 0.f, s1 = 0.f;
    for (int i = t; i < NVC; i += 1024) {
        s0 += expf(lrelu(d_As[2 * i]     + Ad0) - m0);
        s1 += expf(lrelu(d_As[2 * i + 1] + Ad1) - m1);
    }
    sm0[t] = s0; sm1[t] = s1;
    __syncthreads();
    for (int o = 512; o; o >>= 1) {
        if (t < o) { sm0[t] += sm0[t + o]; sm1[t] += sm1[t + o]; }
        __syncthreads();
    }
    if (t == 0) {
        d_vmaxf[0] = m0; d_vmaxf[1] = m1;
        d_vdenf[0] = sm0[0]; d_vdenf[1] = sm1[0];
    }
}
__global__ void vn_agg_k() {   // VAGG_B blocks x 256, partial sums (no atomics)
    int t = threadIdx.x;
    int r0 = blockIdx.x * VROWS;
    int r1 = min(r0 + VROWS, NVC);
    float Ad0 = d_Ad[2 * VN], Ad1 = d_Ad[2 * VN + 1];
    float m0 = d_vmaxf[0], m1 = d_vmaxf[1];
    __shared__ float w0sh[256], w1sh[256];
    float acc = 0.f;
    int head = t >> 7;
    for (int base = r0; base < r1; base += 256) {
        int r = base + t;
        if (r < r1) {
            w0sh[t] = expf(lrelu(d_As[2 * r] + Ad0) - m0);
            w1sh[t] = expf(lrelu(d_As[2 * r + 1] + Ad1) - m1);
        }
        __syncthreads();
        int cnt = min(256, r1 - base);
        const float* wsh = head ? w1sh : w0sh;
        for (int j = 0; j < cnt; j++)
            acc += wsh[j] * d_H[(size_t)(base + j) * DHIDC + t];
        __syncthreads();
    }
    d_vaggp[blockIdx.x][t] = acc;
}
__global__ void vn_fin_k(const float* __restrict__ b, const float* __restrict__ g,
                         const float* __restrict__ be) {
    int t = threadIdx.x;   // 128
    float a0 = 0.f, a1 = 0.f;
    for (int bidx = 0; bidx < VAGG_B; bidx++) {
        a0 += d_vaggp[bidx][t];
        a1 += d_vaggp[bidx][HIDC + t];
    }
    float den0 = d_vdenf[0] + 1e-16f, den1 = d_vdenf[1] + 1e-16f;
    float v = 0.5f * (a0 / den0 + a1 / den1) + b[t];
    __shared__ float sh[HIDC];
    sh[t] = v; __syncthreads();
    for (int o = 64; o; o >>= 1) { if (t < o) sh[t] += sh[t + o]; __syncthreads(); }
    float mu = sh[0] * (1.f / HIDC);
    __syncthreads();
    float dv = v - mu;
    sh[t] = dv * dv; __syncthreads();
    for (int o = 64; o; o >>= 1) { if (t < o) sh[t] += sh[t + o]; __syncthreads(); }
    float var = sh[0] * (1.f / HIDC);
    float y = dv * rsqrtf(var + 1e-5f) * g[t] + be[t];
    float ge = 0.5f * y * (1.f + erff(y * 0.70710678118654752f));
    d_Feat[(size_t)VN * HIDC + t] = ge;
    __nv_bfloat16 h = __float2bfloat16(ge);
    d_Ahi[(size_t)VN * HIDC + t] = h;
    d_Alo[(size_t)VN * HIDC + t] = __float2bfloat16(ge - __bfloat162float(h));
}

// ---------------- LN + GELU epilogue (per-warp, 128 dims) ----------------
__device__ __forceinline__ void ln_epi(int d, int lane, float ax, float ay, float az, float aw,
                                       const float* __restrict__ b, const float* __restrict__ g,
                                       const float* __restrict__ be) {
    const int c = lane * 4;
    float y0 = ax + b[c], y1 = ay + b[c + 1], y2 = az + b[c + 2], y3 = aw + b[c + 3];
    float mu = wsum(y0 + y1 + y2 + y3) * (1.f / HIDC);
    float d0 = y0 - mu, d1 = y1 - mu, d2 = y2 - mu, d3 = y3 - mu;
    float var = wsum(d0 * d0 + d1 * d1 + d2 * d2 + d3 * d3) * (1.f / HIDC);
    float rs = rsqrtf(var + 1e-5f);
    float z0 = d0 * rs * g[c]     + be[c];
    float z1 = d1 * rs * g[c + 1] + be[c + 1];
    float z2 = d2 * rs * g[c + 2] + be[c + 2];
    float z3 = d3 * rs * g[c + 3] + be[c + 3];
    const float kk = 0.70710678118654752f;
    float4 o;
    o.x = 0.5f * z0 * (1.f + erff(z0 * kk));
    o.y = 0.5f * z1 * (1.f + erff(z1 * kk));
    o.z = 0.5f * z2 * (1.f + erff(z2 * kk));
    o.w = 0.5f * z3 * (1.f + erff(z3 * kk));
    *(float4*)&d_Feat[(size_t)d * HIDC + c] = o;
    uint2 hi, lo;
    split2(o.x, o.y, hi.x, lo.x);
    split2(o.z, o.w, hi.y, lo.y);
    *(uint2*)&d_Ahi[(size_t)d * HIDC + c] = hi;
    *(uint2*)&d_Alo[(size_t)d * HIDC + c] = lo;
}

__device__ __forceinline__ void gather_edge(int s, float w0, float w1, int c,
                                            float& ax, float& ay, float& az, float& aw) {
    float4 v0 = *(const float4*)&d_H[(size_t)s * DHIDC + c];
    float4 v1 = *(const float4*)&d_H[(size_t)s * DHIDC + HIDC + c];
    ax += w0 * v0.x + w1 * v1.x;
    ay += w0 * v0.y + w1 * v1.y;
    az += w0 * v0.z + w1 * v1.z;
    aw += w0 * v0.w + w1 * v1.w;
}

// ---------------- fused per-node softmax+aggregate+bias+LN+GELU ----------------
__global__ void node_k(const float* __restrict__ b, const float* __restrict__ g,
                       const float* __restrict__ be) {
    int gid  = blockIdx.x * blockDim.x + threadIdx.x;
    int d    = gid >> 5;
    int lane = gid & 31;
    if (d >= N_NODESC) return;
    const unsigned FULL = 0xffffffffu;
    float Ad0 = d_Ad[2 * d], Ad1 = d_Ad[2 * d + 1];
    int off = d_rowptr[d], end = d_rowptr[d + 1];
    int deg = end - off;

    float ev0 = lrelu(d_As[2 * VN] + Ad0), ev1 = lrelu(d_As[2 * VN + 1] + Ad1);
    float es0 = lrelu(d_As[2 * d]  + Ad0), es1 = lrelu(d_As[2 * d + 1]  + Ad1);

    float ax = 0.f, ay = 0.f, az = 0.f, aw = 0.f;
    const int c = lane * 4;
    float m0, m1, inv0, inv1;

    if (deg <= 32) {
        // ---- fast path: one edge per lane, exps computed once and reused ----
        int s = 0; float l0 = -INFINITY, l1 = -INFINITY;
        if (lane < deg) {
            s  = d_csr[off + lane];
            l0 = lrelu(d_As[2 * s]     + Ad0);
            l1 = lrelu(d_As[2 * s + 1] + Ad1);
        }
        m0 = wmax(fmaxf(l0, fmaxf(ev0, es0)));
        m1 = wmax(fmaxf(l1, fmaxf(ev1, es1)));
        float e0 = (lane < deg) ? expf(l0 - m0) : 0.f;
        float e1 = (lane < deg) ? expf(l1 - m1) : 0.f;
        float den0 = wsum(e0) + expf(ev0 - m0) + expf(es0 - m0);
        float den1 = wsum(e1) + expf(ev1 - m1) + expf(es1 - m1);
        inv0 = 0.5f / (den0 + 1e-16f);
        inv1 = 0.5f / (den1 + 1e-16f);
        float w0 = e0 * inv0, w1 = e1 * inv1;
        for (int j = 0; j < deg; j++) {
            int   sj  = __shfl_sync(FULL, s,  j);
            float w0j = __shfl_sync(FULL, w0, j);
            float w1j = __shfl_sync(FULL, w1, j);
            gather_edge(sj, w0j, w1j, c, ax, ay, az, aw);
        }
    } else {
        // ---- general path ----
        m0 = fmaxf(ev0, es0); m1 = fmaxf(ev1, es1);
        for (int i = off + lane; i < end; i += 32) {
            int s = d_csr[i];
            m0 = fmaxf(m0, lrelu(d_As[2 * s]     + Ad0));
            m1 = fmaxf(m1, lrelu(d_As[2 * s + 1] + Ad1));
        }
        m0 = wmax(m0); m1 = wmax(m1);
        float den0 = 0.f, den1 = 0.f;
        for (int i = off + lane; i < end; i += 32) {
            int s = d_csr[i];
            den0 += expf(lrelu(d_As[2 * s]     + Ad0) - m0);
            den1 += expf(lrelu(d_As[2 * s + 1] + Ad1) - m1);
        }
        den0 = wsum(den0) + expf(ev0 - m0) + expf(es0 - m0);
        den1 = wsum(den1) + expf(ev1 - m1) + expf(es1 - m1);
        inv0 = 0.5f / (den0 + 1e-16f);
        inv1 = 0.5f / (den1 + 1e-16f);
        for (int base = off; base < end; base += 32) {
            int n = min(32, end - base);
            int s = 0; float w0 = 0.f, w1 = 0.f;
            if (lane < n) {
                s  = d_csr[base + lane];
                w0 = expf(lrelu(d_As[2 * s]     + Ad0) - m0) * inv0;
                w1 = expf(lrelu(d_As[2 * s + 1] + Ad1) - m1) * inv1;
            }
            for (int j = 0; j < n; j++) {
                int   sj  = __shfl_sync(FULL, s,  j);
                float w0j = __shfl_sync(FULL, w0, j);
                float w1j = __shfl_sync(FULL, w1, j);
                gather_edge(sj, w0j, w1j, c, ax, ay, az, aw);
            }
        }
    }
    // vnode + self edges
    gather_edge(VN, expf(ev0 - m0) * inv0, expf(ev1 - m1) * inv1, c, ax, ay, az, aw);
    gather_edge(d,  expf(es0 - m0) * inv0, expf(es1 - m1) * inv1, c, ax, ay, az, aw);

    ln_epi(d, lane, ax, ay, az, aw, b, g, be);
}

// ---------------- fp32 f32x2 GEMM (final projection only) ----------------
template<int BN>
__global__ void sgemm_k(const float* __restrict__ A, const float* __restrict__ B,
                        const float* __restrict__ bias, float* __restrict__ C,
                        int M, int K, int N) {
    constexpr int BM = 128, BK = 16, TPB = 2 * BN, GRP = BN / 8;
    __shared__ __align__(16) float2 As2[BK][BM];
    __shared__ __align__(16) float  Bs [BK][BN];
    const int tid = threadIdx.x;
    const int tn = tid % GRP, tm = tid / GRP;
    const int row0 = blockIdx.y * BM, col0 = blockIdx.x * BN;
    unsigned long long acc[8][4];
#pragma unroll
    for (int i = 0; i < 8; i++)
#pragma unroll
        for (int j = 0; j < 4; j++) acc[i][j] = 0ull;
    for (int k0 = 0; k0 < K; k0 += BK) {
        __syncthreads();
#pragma unroll
        for (int s = tid; s < BM * 4; s += TPB) {
            int r = s >> 2, q = s & 3;
            int row = row0 + r;
            float4 v = (row < M) ? *(const float4*)&A[(size_t)row * K + k0 + q * 4]
                                 : make_float4(0.f, 0.f, 0.f, 0.f);
            As2[q * 4 + 0][r] = make_float2(v.x, v.x);
            As2[q * 4 + 1][r] = make_float2(v.y, v.y);
            As2[q * 4 + 2][r] = make_float2(v.z, v.z);
            As2[q * 4 + 3][r] = make_float2(v.w, v.w);
        }
#pragma unroll
        for (int s = tid; s < BK * BN / 4; s += TPB) {
            int br = s / (BN / 4), bc = s % (BN / 4);
            *(float4*)&Bs[br][bc * 4] =
                *(const float4*)&B[(size_t)(k0 + br) * N + col0 + bc * 4];
        }
        __syncthreads();
#pragma unroll
        for (int kk = 0; kk < BK; kk++) {
            unsigned long long a[8], bb[4];
            const ulonglong2* ap = (const ulonglong2*)&As2[kk][tm * 8];
            ulonglong2 a01 = ap[0], a23 = ap[1], a45 = ap[2], a67 = ap[3];
            a[0] = a01.x; a[1] = a01.y; a[2] = a23.x; a[3] = a23.y;
            a[4] = a45.x; a[5] = a45.y; a[6] = a67.x; a[7] = a67.y;
            const ulonglong2* bp = (const ulonglong2*)&Bs[kk][tn * 8];
            ulonglong2 b01 = bp[0], b23 = bp[1];
            bb[0] = b01.x; bb[1] = b01.y; bb[2] = b23.x; bb[3] = b23.y;
#pragma unroll
            for (int i = 0; i < 8; i++)
#pragma unroll
                for (int j = 0; j < 4; j++) ffma2(acc[i][j], a[i], bb[j]);
        }
    }
    float bv[8];
#pragma unroll
    for (int j = 0; j < 8; j++) bv[j] = bias ? bias[col0 + tn * 8 + j] : 0.f;
#pragma unroll
    for (int i = 0; i < 8; i++) {
        int row = row0 + tm * 8 + i;
        if (row < M) {
            float4 o0, o1;
            o0.x = lo32(acc[i][0]) + bv[0]; o0.y = hi32(acc[i][0]) + bv[1];
            o0.z = lo32(acc[i][1]) + bv[2]; o0.w = hi32(acc[i][1]) + bv[3];
            o1.x = lo32(acc[i][2]) + bv[4]; o1.y = hi32(acc[i][2]) + bv[5];
            o1.z = lo32(acc[i][3]) + bv[6]; o1.w = hi32(acc[i][3]) + bv[7];
            *(float4*)&C[(size_t)row * N + col0 + tn * 8]     = o0;
            *(float4*)&C[(size_t)row * N + col0 + tn * 8 + 4] = o1;
        }
    }
}

// ---------------- host launch ----------------
extern "C" void kernel_launch(void* const* d_in, const int* in_sizes, int n_in,
                              void* d_out, int out_size) {
    (void)in_sizes; (void)n_in; (void)out_size;
    const float* X  = (const float*)d_in[0];
    const int*   ei = (const int*)  d_in[1];
    const float* W[3]  = {(const float*)d_in[3],  (const float*)d_in[9],  (const float*)d_in[15]};
    const float* aS[3] = {(const float*)d_in[4],  (const float*)d_in[10], (const float*)d_in[16]};
    const float* aD[3] = {(const float*)d_in[5],  (const float*)d_in[11], (const float*)d_in[17]};
    const float* bb[3] = {(const float*)d_in[6],  (const float*)d_in[12], (const float*)d_in[18]};
    const float* gg[3] = {(const float*)d_in[7],  (const float*)d_in[13], (const float*)d_in[19]};
    const float* bE[3] = {(const float*)d_in[8],  (const float*)d_in[14], (const float*)d_in[20]};
    const float* Wout  = (const float*)d_in[21];
    const float* bout  = (const float*)d_in[22];
    float* out = (float*)d_out;

    float* dFeat; cudaGetSymbolAddress((void**)&dFeat, d_Feat);
    int* dCnt;    cudaGetSymbolAddress((void**)&dCnt, d_cnt);
    __nv_bfloat16 *dBhi, *dBlo;
    cudaGetSymbolAddress((void**)&dBhi, d_Bhi);
    cudaGetSymbolAddress((void**)&dBlo, d_Blo);

    // weights for all layers (one launch)
    const int wtot = DHIDC * IN_DIMC + 2 * DHIDC * HIDC;
    convw_all_k<<<(wtot + 255) / 256, 256>>>(W[0], W[1], W[2]);

    // vnode mean + bf16 split of layer0 input
    vacc_zero_k<<<1, IN_DIMC>>>();
    vnode_partial_k<<<512, IN_DIMC>>>(X);
    convx0_k<<<(int)(((size_t)NVC * IN_DIMC / 4 + 255) / 256), 256>>>(X);

    // CSR
    cudaMemsetAsync(dCnt, 0, N_NODESC * sizeof(int), 0);
    const int eb = (NEC + 255) / 256;
    hist_k<<<eb, 256>>>(ei);
    scanb_k<<<1, 128>>>();
    rowptr_k<<<NB_SCAN, 512>>>();
    scatter_k<<<eb, 256>>>(ei);

    const int node_blocks  = (N_NODESC * 32 + 255) / 256;
    const int alpha_blocks = (NVC * 32 + 255) / 256;

    for (int l = 0; l < 3; l++) {
        int K = (l == 0) ? IN_DIMC : HIDC;
        dim3 grid(DHIDC / 128, MTILES);
        wgemm_k<<<grid, 256>>>(dBhi + (size_t)l * DHIDC * IN_DIMC,
                               dBlo + (size_t)l * DHIDC * IN_DIMC, K);
        alpha_k<<<alpha_blocks, 256>>>(aS[l], aD[l]);
        vn_pre_k<<<1, 1024>>>();
        vn_agg_k<<<VAGG_B, 256>>>();
        vn_fin_k<<<1, HIDC>>>(bb[l], gg[l], bE[l]);
        node_k<<<node_blocks, 256>>>(bb[l], gg[l], bE[l]);
    }

    dim3 gridF(1, (N_NODESC + 127) / 128);
    sgemm_k<64><<<gridF, 128>>>(dFeat, Wout, bout, out, N_NODESC, HIDC, OUT_DIMC);
}

// round 9
// speedup vs baseline: 1.3853x; 1.2500x over previous
#include <cuda_runtime.h>
#include <cuda_bf16.h>
#include <mma.h>
#include <math.h>
#include <stdint.h>

using namespace nvcuda;

// ---------------- problem constants ----------------
#define N_NODESC 50000
#define NVC      50001
#define NPAD     50048
#define VN       N_NODESC
#define NEC      400000
#define IN_DIMC  256
#define HIDC     128
#define DHIDC    256
#define OUT_DIMC 64
#define NB_SCAN  98
#define VROWS    391
#define MTILES   391
#define VAGG_B   128

// ---------------- scratch ----------------
__device__ __align__(16) float d_H   [(size_t)NPAD * DHIDC];
__device__ __align__(16) float d_Feat[(size_t)NVC * HIDC];
__device__ __align__(16) __nv_bfloat16 d_Ahi[(size_t)NPAD * IN_DIMC];
__device__ __align__(16) __nv_bfloat16 d_Alo[(size_t)NPAD * IN_DIMC];
__device__ __align__(16) __nv_bfloat16 d_Bhi[3][DHIDC * IN_DIMC];
__device__ __align__(16) __nv_bfloat16 d_Blo[3][DHIDC * IN_DIMC];
__device__ float d_As[NVC * 2];
__device__ float d_Ad[NVC * 2];
__device__ int   d_cnt   [N_NODESC];
__device__ int   d_rowptr[N_NODESC + 1];
__device__ int   d_cursor[N_NODESC];
__device__ int   d_csr   [NEC];
__device__ int   d_bsumex[NB_SCAN + 1];
__device__ float d_vacc[IN_DIMC];
__device__ float d_vmaxf[2];
__device__ float d_vdenf[2];
__device__ float d_vaggp[VAGG_B][DHIDC];

// ---------------- helpers ----------------
__device__ __forceinline__ float lrelu(float v) { return v > 0.f ? v : 0.2f * v; }
__device__ __forceinline__ float wsum(float v) {
#pragma unroll
    for (int o = 16; o; o >>= 1) v += __shfl_xor_sync(0xffffffffu, v, o);
    return v;
}
__device__ __forceinline__ float wmax(float v) {
#pragma unroll
    for (int o = 16; o; o >>= 1) v = fmaxf(v, __shfl_xor_sync(0xffffffffu, v, o));
    return v;
}
__device__ __forceinline__ void ffma2(unsigned long long& d, unsigned long long a,
                                      unsigned long long b) {
    asm("fma.rn.f32x2 %0, %1, %2, %0;" : "+l"(d) : "l"(a), "l"(b));
}
__device__ __forceinline__ float lo32(unsigned long long v) { return __uint_as_float((unsigned)v); }
__device__ __forceinline__ float hi32(unsigned long long v) { return __uint_as_float((unsigned)(v >> 32)); }

__device__ __forceinline__ void split2(float a, float b, unsigned& hi, unsigned& lo) {
    __nv_bfloat16 ha = __float2bfloat16(a), hb = __float2bfloat16(b);
    __nv_bfloat16 la = __float2bfloat16(a - __bfloat162float(ha));
    __nv_bfloat16 lb = __float2bfloat16(b - __bfloat162float(hb));
    __nv_bfloat162 H = {ha, hb}, L = {la, lb};
    hi = *(unsigned*)&H;  lo = *(unsigned*)&L;
}
__device__ __forceinline__ void cp16(__nv_bfloat16* dst, const __nv_bfloat16* src) {
    uint32_t d = (uint32_t)__cvta_generic_to_shared(dst);
    asm volatile("cp.async.cg.shared.global [%0], [%1], 16;" :: "r"(d), "l"(src));
}

// ---------------- vnode input mean ----------------
__global__ void vacc_zero_k() { d_vacc[threadIdx.x] = 0.f; }
__global__ void vnode_partial_k(const float* __restrict__ X) {
    int t = threadIdx.x;
    float loc = 0.f;
    for (int r = blockIdx.x; r < N_NODESC; r += gridDim.x)
        loc += X[(size_t)r * IN_DIMC + t];
    atomicAdd(&d_vacc[t], loc);
}

// ---------------- conversions ----------------
__global__ void convx0_k(const float* __restrict__ X) {
    size_t i4 = (size_t)blockIdx.x * blockDim.x + threadIdx.x;
    if (i4 >= (size_t)NVC * IN_DIMC / 4) return;
    size_t i = i4 * 4;
    int row = (int)(i / IN_DIMC);
    int k   = (int)(i % IN_DIMC);
    float4 v;
    if (row < N_NODESC) v = *(const float4*)&X[i];
    else {
        const float inv = 1.f / (float)N_NODESC;
        v.x = d_vacc[k] * inv; v.y = d_vacc[k + 1] * inv;
        v.z = d_vacc[k + 2] * inv; v.w = d_vacc[k + 3] * inv;
    }
    uint2 hi, lo;
    split2(v.x, v.y, hi.x, lo.x);
    split2(v.z, v.w, hi.y, lo.y);
    *(uint2*)&d_Ahi[i] = hi;
    *(uint2*)&d_Alo[i] = lo;
}
__global__ void convw_all_k(const float* __restrict__ W0, const float* __restrict__ W1,
                            const float* __restrict__ W2) {
    int idx = blockIdx.x * blockDim.x + threadIdx.x;
    int l, K; const float* W; int base = idx;
    if (base < DHIDC * IN_DIMC)      { l = 0; K = IN_DIMC; W = W0; }
    else if ((base -= DHIDC * IN_DIMC) < DHIDC * HIDC) { l = 1; K = HIDC; W = W1; }
    else if ((base -= DHIDC * HIDC) < DHIDC * HIDC)    { l = 2; K = HIDC; W = W2; }
    else return;
    int n = base / K, k = base % K;
    float v = W[(size_t)k * DHIDC + n];
    __nv_bfloat16 h = __float2bfloat16(v);
    d_Bhi[l][n * K + k] = h;
    d_Blo[l][n * K + k] = __float2bfloat16(v - __bfloat162float(h));
}

// ---------------- CSR build ----------------
__global__ void hist_k(const int* __restrict__ ei) {
    int e = blockIdx.x * blockDim.x + threadIdx.x;
    if (e < NEC) atomicAdd(&d_cnt[ei[NEC + e]], 1);
}
__global__ void scanb_k() {
    __shared__ int bs[NB_SCAN];
    int b = threadIdx.x;
    if (b < NB_SCAN) {
        int s = 0;
        int base = b * 512;
#pragma unroll 8
        for (int i = 0; i < 512; i++) {
            int idx = base + i;
            if (idx < N_NODESC) s += d_cnt[idx];
        }
        bs[b] = s;
    }
    __syncthreads();
    if (threadIdx.x == 0) {
        int carry = 0;
        for (int i = 0; i < NB_SCAN; i++) { d_bsumex[i] = carry; carry += bs[i]; }
        d_bsumex[NB_SCAN] = carry;
    }
}
__global__ void rowptr_k() {
    __shared__ int sh[512];
    int t = threadIdx.x;
    int idx = blockIdx.x * 512 + t;
    int c = (idx < N_NODESC) ? d_cnt[idx] : 0;
    sh[t] = c;
    __syncthreads();
#pragma unroll
    for (int o = 1; o < 512; o <<= 1) {
        int v = (t >= o) ? sh[t - o] : 0;
        __syncthreads();
        sh[t] += v;
        __syncthreads();
    }
    if (idx < N_NODESC) {
        int p = d_bsumex[blockIdx.x] + sh[t] - c;
        d_rowptr[idx] = p;
        d_cursor[idx] = p;
    }
    if (idx == 0) d_rowptr[N_NODESC] = NEC;
}
__global__ void scatter_k(const int* __restrict__ ei) {
    int e = blockIdx.x * blockDim.x + threadIdx.x;
    if (e >= NEC) return;
    int d = ei[NEC + e];
    int p = atomicAdd(&d_cursor[d], 1);
    d_csr[p] = ei[e];
}

// ---------------- wmma bf16 hi/lo GEMM with cp.async double buffering ----------------
#define SSTR 48
#define ARR_E  (128 * SSTR)          // elements per tile array (6144)
#define BUF_E  (4 * ARR_E)           // elements per buffer (24576)
#define WG_SMEM (2 * BUF_E * 2)      // bytes (98304)

__global__ void __launch_bounds__(256) wgemm_k(const __nv_bfloat16* __restrict__ Bhi,
                                               const __nv_bfloat16* __restrict__ Blo,
                                               int K) {
    extern __shared__ __align__(128) __nv_bfloat16 sm[];
    const int tid = threadIdx.x;
    const int wid = tid >> 5;
    const int wm = wid & 3;
    const int wn = wid >> 2;
    const int row0 = blockIdx.y * 128;
    const int col0 = blockIdx.x * 128;

    wmma::fragment<wmma::accumulator, 16, 16, 16, float> acc[2][4];
#pragma unroll
    for (int i = 0; i < 2; i++)
#pragma unroll
        for (int j = 0; j < 4; j++) wmma::fill_fragment(acc[i][j], 0.f);

    const int nch = K >> 5;

    auto issue = [&](int c, int buf) {
        const int k0 = c << 5;
        __nv_bfloat16* base = sm + buf * BUF_E;
#pragma unroll
        for (int s = tid; s < 512; s += 256) {
            int r = s >> 2, q = s & 3;
            size_t ga = (size_t)(row0 + r) * K + k0 + q * 8;
            size_t gb = (size_t)(col0 + r) * K + k0 + q * 8;
            int so = r * SSTR + q * 8;
            cp16(base + so,             &d_Ahi[ga]);
            cp16(base + ARR_E + so,     &d_Alo[ga]);
            cp16(base + 2 * ARR_E + so, &Bhi[gb]);
            cp16(base + 3 * ARR_E + so, &Blo[gb]);
        }
        asm volatile("cp.async.commit_group;");
    };

    issue(0, 0);
    for (int c = 0; c < nch; c++) {
        const int buf = c & 1;
        if (c + 1 < nch) {
            issue(c + 1, buf ^ 1);
            asm volatile("cp.async.wait_group 1;");
        } else {
            asm volatile("cp.async.wait_group 0;");
        }
        __syncthreads();

        const __nv_bfloat16* Ah = sm + buf * BUF_E;
        const __nv_bfloat16* Al = Ah + ARR_E;
        const __nv_bfloat16* Bh = Ah + 2 * ARR_E;
        const __nv_bfloat16* Bl = Ah + 3 * ARR_E;
#pragma unroll
        for (int kk = 0; kk < 32; kk += 16) {
            wmma::fragment<wmma::matrix_a, 16, 16, 16, __nv_bfloat16, wmma::row_major> ah[2], al[2];
#pragma unroll
            for (int i = 0; i < 2; i++) {
                wmma::load_matrix_sync(ah[i], Ah + (wm * 32 + i * 16) * SSTR + kk, SSTR);
                wmma::load_matrix_sync(al[i], Al + (wm * 32 + i * 16) * SSTR + kk, SSTR);
            }
#pragma unroll
            for (int j = 0; j < 4; j++) {
                wmma::fragment<wmma::matrix_b, 16, 16, 16, __nv_bfloat16, wmma::col_major> bh, bl;
                wmma::load_matrix_sync(bh, Bh + (wn * 64 + j * 16) * SSTR + kk, SSTR);
                wmma::load_matrix_sync(bl, Bl + (wn * 64 + j * 16) * SSTR + kk, SSTR);
#pragma unroll
                for (int i = 0; i < 2; i++) {
                    wmma::mma_sync(acc[i][j], ah[i], bh, acc[i][j]);
                    wmma::mma_sync(acc[i][j], ah[i], bl, acc[i][j]);
                    wmma::mma_sync(acc[i][j], al[i], bh, acc[i][j]);
                }
            }
        }
        __syncthreads();
    }
#pragma unroll
    for (int i = 0; i < 2; i++)
#pragma unroll
        for (int j = 0; j < 4; j++)
            wmma::store_matrix_sync(
                &d_H[(size_t)(row0 + wm * 32 + i * 16) * DHIDC + col0 + wn * 64 + j * 16],
                acc[i][j], DHIDC, wmma::mem_row_major);
}

// ---------------- attention logits: warp per node ----------------
__global__ void alpha_k(const float* __restrict__ asrc,
                        const float* __restrict__ adst) {
    int gid  = blockIdx.x * blockDim.x + threadIdx.x;
    int n    = gid >> 5;
    int lane = gid & 31;
    if (n >= NVC) return;
    const int c = lane * 4;
    float4 h0 = *(const float4*)&d_H[(size_t)n * DHIDC + c];
    float4 h1 = *(const float4*)&d_H[(size_t)n * DHIDC + HIDC + c];
    float4 s0 = *(const float4*)&asrc[c];
    float4 s1 = *(const float4*)&asrc[HIDC + c];
    float4 e0 = *(const float4*)&adst[c];
    float4 e1 = *(const float4*)&adst[HIDC + c];
    float as0 = h0.x * s0.x + h0.y * s0.y + h0.z * s0.z + h0.w * s0.w;
    float as1 = h1.x * s1.x + h1.y * s1.y + h1.z * s1.z + h1.w * s1.w;
    float ad0 = h0.x * e0.x + h0.y * e0.y + h0.z * e0.z + h0.w * e0.w;
    float ad1 = h1.x * e1.x + h1.y * e1.y + h1.z * e1.z + h1.w * e1.w;
    as0 = wsum(as0); as1 = wsum(as1); ad0 = wsum(ad0); ad1 = wsum(ad1);
    if (lane == 0) {
        d_As[2 * n] = as0; d_As[2 * n + 1] = as1;
        d_Ad[2 * n] = ad0; d_Ad[2 * n + 1] = ad1;
    }
}

// ---------------- vnode chain ----------------
__global__ void vn_pre_k() {
    __shared__ float sm0[1024], sm1[1024];
    int t = threadIdx.x;
    float Ad0 = d_Ad[2 * VN], Ad1 = d_Ad[2 * VN + 1];
    float m0 = -INFINITY, m1 = -INFINITY;
    for (int i = t; i < NVC; i += 1024) {
        m0 = fmaxf(m0, lrelu(d_As[2 * i]     + Ad0));
        m1 = fmaxf(m1, lrelu(d_As[2 * i + 1] + Ad1));
    }
    sm0[t] = m0; sm1[t] = m1;
    __syncthreads();
    for (int o = 512; o; o >>= 1) {
        if (t < o) { sm0[t] = fmaxf(sm0[t], sm0[t + o]); sm1[t] = fmaxf(sm1[t], sm1[t + o]); }
        __syncthreads();
    }
    m0 = sm0[0]; m1 = sm1[0];
    __syncthreads();
    float s0 = 0.f, s1 = 0.f;
    for (int i = t; i < NVC; i += 1024) {
        s0 += expf(lrelu(d_As[2 * i]     + Ad0) - m0);
        s1 += expf(lrelu(d_As[2 * i + 1] + Ad1) - m1);
    }
    sm0[t] = s0; sm1[t] = s1;
    __syncthreads();
    for (int o = 512; o; o >>= 1) {
        if (t < o) { sm0[t] += sm0[t + o]; sm1[t] += sm1[t + o]; }
        __syncthreads();
    }
    if (t == 0) {
        d_vmaxf[0] = m0; d_vmaxf[1] = m1;
        d_vdenf[0] = sm0[0]; d_vdenf[1] = sm1[0];
    }
}
__global__ void vn_agg_k() {
    int t = threadIdx.x;
    int r0 = blockIdx.x * VROWS;
    int r1 = min(r0 + VROWS, NVC);
    float Ad0 = d_Ad[2 * VN], Ad1 = d_Ad[2 * VN + 1];
    float m0 = d_vmaxf[0], m1 = d_vmaxf[1];
    __shared__ float w0sh[256], w1sh[256];
    float acc = 0.f;
    int head = t >> 7;
    for (int base = r0; base < r1; base += 256) {
        int r = base + t;
        if (r < r1) {
            w0sh[t] = expf(lrelu(d_As[2 * r] + Ad0) - m0);
            w1sh[t] = expf(lrelu(d_As[2 * r + 1] + Ad1) - m1);
        }
        __syncthreads();
        int cnt = min(256, r1 - base);
        const float* wsh = head ? w1sh : w0sh;
        for (int j = 0; j < cnt; j++)
            acc += wsh[j] * d_H[(size_t)(base + j) * DHIDC + t];
        __syncthreads();
    }
    d_vaggp[blockIdx.x][t] = acc;
}
__global__ void vn_fin_k(const float* __restrict__ b, const float* __restrict__ g,
                         const float* __restrict__ be) {
    int t = threadIdx.x;
    float a0 = 0.f, a1 = 0.f;
    for (int bidx = 0; bidx < VAGG_B; bidx++) {
        a0 += d_vaggp[bidx][t];
        a1 += d_vaggp[bidx][HIDC + t];
    }
    float den0 = d_vdenf[0] + 1e-16f, den1 = d_vdenf[1] + 1e-16f;
    float v = 0.5f * (a0 / den0 + a1 / den1) + b[t];
    __shared__ float sh[HIDC];
    sh[t] = v; __syncthreads();
    for (int o = 64; o; o >>= 1) { if (t < o) sh[t] += sh[t + o]; __syncthreads(); }
    float mu = sh[0] * (1.f / HIDC);
    __syncthreads();
    float dv = v - mu;
    sh[t] = dv * dv; __syncthreads();
    for (int o = 64; o; o >>= 1) { if (t < o) sh[t] += sh[t + o]; __syncthreads(); }
    float var = sh[0] * (1.f / HIDC);
    float y = dv * rsqrtf(var + 1e-5f) * g[t] + be[t];
    float ge = 0.5f * y * (1.f + erff(y * 0.70710678118654752f));
    d_Feat[(size_t)VN * HIDC + t] = ge;
    __nv_bfloat16 h = __float2bfloat16(ge);
    d_Ahi[(size_t)VN * HIDC + t] = h;
    d_Alo[(size_t)VN * HIDC + t] = __float2bfloat16(ge - __bfloat162float(h));
}

// ---------------- node epilogue helpers ----------------
__device__ __forceinline__ void ln_epi(int d, int lane, float ax, float ay, float az, float aw,
                                       const float* __restrict__ b, const float* __restrict__ g,
                                       const float* __restrict__ be) {
    const int c = lane * 4;
    float y0 = ax + b[c], y1 = ay + b[c + 1], y2 = az + b[c + 2], y3 = aw + b[c + 3];
    float mu = wsum(y0 + y1 + y2 + y3) * (1.f / HIDC);
    float d0 = y0 - mu, d1 = y1 - mu, d2 = y2 - mu, d3 = y3 - mu;
    float var = wsum(d0 * d0 + d1 * d1 + d2 * d2 + d3 * d3) * (1.f / HIDC);
    float rs = rsqrtf(var + 1e-5f);
    float z0 = d0 * rs * g[c]     + be[c];
    float z1 = d1 * rs * g[c + 1] + be[c + 1];
    float z2 = d2 * rs * g[c + 2] + be[c + 2];
    float z3 = d3 * rs * g[c + 3] + be[c + 3];
    const float kk = 0.70710678118654752f;
    float4 o;
    o.x = 0.5f * z0 * (1.f + erff(z0 * kk));
    o.y = 0.5f * z1 * (1.f + erff(z1 * kk));
    o.z = 0.5f * z2 * (1.f + erff(z2 * kk));
    o.w = 0.5f * z3 * (1.f + erff(z3 * kk));
    *(float4*)&d_Feat[(size_t)d * HIDC + c] = o;
    uint2 hi, lo;
    split2(o.x, o.y, hi.x, lo.x);
    split2(o.z, o.w, hi.y, lo.y);
    *(uint2*)&d_Ahi[(size_t)d * HIDC + c] = hi;
    *(uint2*)&d_Alo[(size_t)d * HIDC + c] = lo;
}
__device__ __forceinline__ void gather_edge(int s, float w0, float w1, int c,
                                            float& ax, float& ay, float& az, float& aw) {
    float4 v0 = *(const float4*)&d_H[(size_t)s * DHIDC + c];
    float4 v1 = *(const float4*)&d_H[(size_t)s * DHIDC + HIDC + c];
    ax += w0 * v0.x + w1 * v1.x;
    ay += w0 * v0.y + w1 * v1.y;
    az += w0 * v0.z + w1 * v1.z;
    aw += w0 * v0.w + w1 * v1.w;
}

// ---------------- fused per-node softmax+aggregate+bias+LN+GELU ----------------
__global__ void node_k(const float* __restrict__ b, const float* __restrict__ g,
                       const float* __restrict__ be) {
    int gid  = blockIdx.x * blockDim.x + threadIdx.x;
    int d    = gid >> 5;
    int lane = gid & 31;
    if (d >= N_NODESC) return;
    const unsigned FULL = 0xffffffffu;
    float Ad0 = d_Ad[2 * d], Ad1 = d_Ad[2 * d + 1];
    int off = d_rowptr[d], end = d_rowptr[d + 1];
    int deg = end - off;

    float ev0 = lrelu(d_As[2 * VN] + Ad0), ev1 = lrelu(d_As[2 * VN + 1] + Ad1);
    float es0 = lrelu(d_As[2 * d]  + Ad0), es1 = lrelu(d_As[2 * d + 1]  + Ad1);

    float ax = 0.f, ay = 0.f, az = 0.f, aw = 0.f;
    const int c = lane * 4;
    float m0, m1, inv0, inv1;

    if (deg <= 32) {
        int s = 0; float l0 = -INFINITY, l1 = -INFINITY;
        if (lane < deg) {
            s  = d_csr[off + lane];
            l0 = lrelu(d_As[2 * s]     + Ad0);
            l1 = lrelu(d_As[2 * s + 1] + Ad1);
        }
        m0 = wmax(fmaxf(l0, fmaxf(ev0, es0)));
        m1 = wmax(fmaxf(l1, fmaxf(ev1, es1)));
        float e0 = (lane < deg) ? expf(l0 - m0) : 0.f;
        float e1 = (lane < deg) ? expf(l1 - m1) : 0.f;
        float den0 = wsum(e0) + expf(ev0 - m0) + expf(es0 - m0);
        float den1 = wsum(e1) + expf(ev1 - m1) + expf(es1 - m1);
        inv0 = 0.5f / (den0 + 1e-16f);
        inv1 = 0.5f / (den1 + 1e-16f);
        float w0 = e0 * inv0, w1 = e1 * inv1;
        for (int j = 0; j < deg; j++) {
            int   sj  = __shfl_sync(FULL, s,  j);
            float w0j = __shfl_sync(FULL, w0, j);
            float w1j = __shfl_sync(FULL, w1, j);
            gather_edge(sj, w0j, w1j, c, ax, ay, az, aw);
        }
    } else {
        m0 = fmaxf(ev0, es0); m1 = fmaxf(ev1, es1);
        for (int i = off + lane; i < end; i += 32) {
            int s = d_csr[i];
            m0 = fmaxf(m0, lrelu(d_As[2 * s]     + Ad0));
            m1 = fmaxf(m1, lrelu(d_As[2 * s + 1] + Ad1));
        }
        m0 = wmax(m0); m1 = wmax(m1);
        float den0 = 0.f, den1 = 0.f;
        for (int i = off + lane; i < end; i += 32) {
            int s = d_csr[i];
            den0 += expf(lrelu(d_As[2 * s]     + Ad0) - m0);
            den1 += expf(lrelu(d_As[2 * s + 1] + Ad1) - m1);
        }
        den0 = wsum(den0) + expf(ev0 - m0) + expf(es0 - m0);
        den1 = wsum(den1) + expf(ev1 - m1) + expf(es1 - m1);
        inv0 = 0.5f / (den0 + 1e-16f);
        inv1 = 0.5f / (den1 + 1e-16f);
        for (int base = off; base < end; base += 32) {
            int n = min(32, end - base);
            int s = 0; float w0 = 0.f, w1 = 0.f;
            if (lane < n) {
                s  = d_csr[base + lane];
                w0 = expf(lrelu(d_As[2 * s]     + Ad0) - m0) * inv0;
                w1 = expf(lrelu(d_As[2 * s + 1] + Ad1) - m1) * inv1;
            }
            for (int j = 0; j < n; j++) {
                int   sj  = __shfl_sync(FULL, s,  j);
                float w0j = __shfl_sync(FULL, w0, j);
                float w1j = __shfl_sync(FULL, w1, j);
                gather_edge(sj, w0j, w1j, c, ax, ay, az, aw);
            }
        }
    }
    gather_edge(VN, expf(ev0 - m0) * inv0, expf(ev1 - m1) * inv1, c, ax, ay, az, aw);
    gather_edge(d,  expf(es0 - m0) * inv0, expf(es1 - m1) * inv1, c, ax, ay, az, aw);

    ln_epi(d, lane, ax, ay, az, aw, b, g, be);
}

// ---------------- fp32 f32x2 GEMM (final projection) ----------------
template<int BN>
__global__ void sgemm_k(const float* __restrict__ A, const float* __restrict__ B,
                        const float* __restrict__ bias, float* __restrict__ C,
                        int M, int K, int N) {
    constexpr int BM = 128, BK = 16, TPB = 2 * BN, GRP = BN / 8;
    __shared__ __align__(16) float2 As2[BK][BM];
    __shared__ __align__(16) float  Bs [BK][BN];
    const int tid = threadIdx.x;
    const int tn = tid % GRP, tm = tid / GRP;
    const int row0 = blockIdx.y * BM, col0 = blockIdx.x * BN;
    unsigned long long acc[8][4];
#pragma unroll
    for (int i = 0; i < 8; i++)
#pragma unroll
        for (int j = 0; j < 4; j++) acc[i][j] = 0ull;
    for (int k0 = 0; k0 < K; k0 += BK) {
        __syncthreads();
#pragma unroll
        for (int s = tid; s < BM * 4; s += TPB) {
            int r = s >> 2, q = s & 3;
            int row = row0 + r;
            float4 v = (row < M) ? *(const float4*)&A[(size_t)row * K + k0 + q * 4]
                                 : make_float4(0.f, 0.f, 0.f, 0.f);
            As2[q * 4 + 0][r] = make_float2(v.x, v.x);
            As2[q * 4 + 1][r] = make_float2(v.y, v.y);
            As2[q * 4 + 2][r] = make_float2(v.z, v.z);
            As2[q * 4 + 3][r] = make_float2(v.w, v.w);
        }
#pragma unroll
        for (int s = tid; s < BK * BN / 4; s += TPB) {
            int br = s / (BN / 4), bc = s % (BN / 4);
            *(float4*)&Bs[br][bc * 4] =
                *(const float4*)&B[(size_t)(k0 + br) * N + col0 + bc * 4];
        }
        __syncthreads();
#pragma unroll
        for (int kk = 0; kk < BK; kk++) {
            unsigned long long a[8], bb[4];
            const ulonglong2* ap = (const ulonglong2*)&As2[kk][tm * 8];
            ulonglong2 a01 = ap[0], a23 = ap[1], a45 = ap[2], a67 = ap[3];
            a[0] = a01.x; a[1] = a01.y; a[2] = a23.x; a[3] = a23.y;
            a[4] = a45.x; a[5] = a45.y; a[6] = a67.x; a[7] = a67.y;
            const ulonglong2* bp = (const ulonglong2*)&Bs[kk][tn * 8];
            ulonglong2 b01 = bp[0], b23 = bp[1];
            bb[0] = b01.x; bb[1] = b01.y; bb[2] = b23.x; bb[3] = b23.y;
#pragma unroll
            for (int i = 0; i < 8; i++)
#pragma unroll
                for (int j = 0; j < 4; j++) ffma2(acc[i][j], a[i], bb[j]);
        }
    }
    float bv[8];
#pragma unroll
    for (int j = 0; j < 8; j++) bv[j] = bias ? bias[col0 + tn * 8 + j] : 0.f;
#pragma unroll
    for (int i = 0; i < 8; i++) {
        int row = row0 + tm * 8 + i;
        if (row < M) {
            float4 o0, o1;
            o0.x = lo32(acc[i][0]) + bv[0]; o0.y = hi32(acc[i][0]) + bv[1];
            o0.z = lo32(acc[i][1]) + bv[2]; o0.w = hi32(acc[i][1]) + bv[3];
            o1.x = lo32(acc[i][2]) + bv[4]; o1.y = hi32(acc[i][2]) + bv[5];
            o1.z = lo32(acc[i][3]) + bv[6]; o1.w = hi32(acc[i][3]) + bv[7];
            *(float4*)&C[(size_t)row * N + col0 + tn * 8]     = o0;
            *(float4*)&C[(size_t)row * N + col0 + tn * 8 + 4] = o1;
        }
    }
}

// ---------------- host launch ----------------
extern "C" void kernel_launch(void* const* d_in, const int* in_sizes, int n_in,
                              void* d_out, int out_size) {
    (void)in_sizes; (void)n_in; (void)out_size;
    const float* X  = (const float*)d_in[0];
    const int*   ei = (const int*)  d_in[1];
    const float* W[3]  = {(const float*)d_in[3],  (const float*)d_in[9],  (const float*)d_in[15]};
    const float* aS[3] = {(const float*)d_in[4],  (const float*)d_in[10], (const float*)d_in[16]};
    const float* aD[3] = {(const float*)d_in[5],  (const float*)d_in[11], (const float*)d_in[17]};
    const float* bb[3] = {(const float*)d_in[6],  (const float*)d_in[12], (const float*)d_in[18]};
    const float* gg[3] = {(const float*)d_in[7],  (const float*)d_in[13], (const float*)d_in[19]};
    const float* bE[3] = {(const float*)d_in[8],  (const float*)d_in[14], (const float*)d_in[20]};
    const float* Wout  = (const float*)d_in[21];
    const float* bout  = (const float*)d_in[22];
    float* out = (float*)d_out;

    float* dFeat; cudaGetSymbolAddress((void**)&dFeat, d_Feat);
    int* dCnt;    cudaGetSymbolAddress((void**)&dCnt, d_cnt);
    __nv_bfloat16 *dBhi, *dBlo;
    cudaGetSymbolAddress((void**)&dBhi, d_Bhi);
    cudaGetSymbolAddress((void**)&dBlo, d_Blo);

    static cudaStream_t sB = nullptr, sC = nullptr;
    static cudaEvent_t evF = nullptr, evJ = nullptr, evC0 = nullptr, evCJ = nullptr;
    if (!sB) {
        cudaStreamCreateWithFlags(&sB, cudaStreamNonBlocking);
        cudaStreamCreateWithFlags(&sC, cudaStreamNonBlocking);
        cudaEventCreateWithFlags(&evF,  cudaEventDisableTiming);
        cudaEventCreateWithFlags(&evJ,  cudaEventDisableTiming);
        cudaEventCreateWithFlags(&evC0, cudaEventDisableTiming);
        cudaEventCreateWithFlags(&evCJ, cudaEventDisableTiming);
        cudaFuncSetAttribute(wgemm_k, cudaFuncAttributeMaxDynamicSharedMemorySize, WG_SMEM);
    }

    // --- fork CSR build onto sC (joined before first node_k) ---
    cudaEventRecord(evC0, 0);
    cudaStreamWaitEvent(sC, evC0, 0);
    cudaMemsetAsync(dCnt, 0, N_NODESC * sizeof(int), sC);
    const int eb = (NEC + 255) / 256;
    hist_k<<<eb, 256, 0, sC>>>(ei);
    scanb_k<<<1, 128, 0, sC>>>();
    rowptr_k<<<NB_SCAN, 512, 0, sC>>>();
    scatter_k<<<eb, 256, 0, sC>>>(ei);
    cudaEventRecord(evCJ, sC);

    // --- main stream: weights, vnode mean, layer0 input split ---
    const int wtot = DHIDC * IN_DIMC + 2 * DHIDC * HIDC;
    convw_all_k<<<(wtot + 255) / 256, 256>>>(W[0], W[1], W[2]);
    vacc_zero_k<<<1, IN_DIMC>>>();
    vnode_partial_k<<<512, IN_DIMC>>>(X);
    convx0_k<<<(int)(((size_t)NVC * IN_DIMC / 4 + 255) / 256), 256>>>(X);

    const int node_blocks  = (N_NODESC * 32 + 255) / 256;
    const int alpha_blocks = (NVC * 32 + 255) / 256;

    for (int l = 0; l < 3; l++) {
        int K = (l == 0) ? IN_DIMC : HIDC;
        dim3 grid(DHIDC / 128, MTILES);
        wgemm_k<<<grid, 256, WG_SMEM>>>(dBhi + (size_t)l * DHIDC * IN_DIMC,
                                        dBlo + (size_t)l * DHIDC * IN_DIMC, K);
        alpha_k<<<alpha_blocks, 256>>>(aS[l], aD[l]);

        // fork: vnode chain on sB, node_k on main (independent of each other)
        cudaEventRecord(evF, 0);
        cudaStreamWaitEvent(sB, evF, 0);
        vn_pre_k<<<1, 1024, 0, sB>>>();
        vn_agg_k<<<VAGG_B, 256, 0, sB>>>();
        vn_fin_k<<<1, HIDC, 0, sB>>>(bb[l], gg[l], bE[l]);

        if (l == 0) cudaStreamWaitEvent(0, evCJ, 0);
        node_k<<<node_blocks, 256>>>(bb[l], gg[l], bE[l]);

        cudaEventRecord(evJ, sB);
        cudaStreamWaitEvent(0, evJ, 0);
    }

    dim3 gridF(1, (N_NODESC + 127) / 128);
    sgemm_k<64><<<gridF, 128>>>(dFeat, Wout, bout, out, N_NODESC, HIDC, OUT_DIMC);
}

// round 11
// speedup vs baseline: 1.6108x; 1.1628x over previous
#include <cuda_runtime.h>
#include <cuda_bf16.h>
#include <cuda_fp16.h>
#include <mma.h>
#include <math.h>
#include <stdint.h>

using namespace nvcuda;

// ---------------- problem constants ----------------
#define N_NODESC 50000
#define NVC      50001
#define NPAD     50048
#define VN       N_NODESC
#define NEC      400000
#define IN_DIMC  256
#define HIDC     128
#define DHIDC    256
#define OUT_DIMC 64
#define NB_SCAN  98
#define VROWS    391
#define MTILES   391
#define VAGG_B   128

// ---------------- scratch ----------------
__device__ __align__(16) __half d_Hh  [(size_t)NPAD * DHIDC];    // fp16 H for gathers
__device__ __align__(16) float d_Feat[(size_t)NVC * HIDC];
__device__ __align__(16) __nv_bfloat16 d_Ahi[(size_t)NPAD * IN_DIMC];
__device__ __align__(16) __nv_bfloat16 d_Alo[(size_t)NPAD * IN_DIMC];
__device__ __align__(16) __nv_bfloat16 d_Bhi[3][DHIDC * IN_DIMC];
__device__ __align__(16) __nv_bfloat16 d_Blo[3][DHIDC * IN_DIMC];
__device__ float d_As[NPAD * 2];
__device__ float d_Ad[NPAD * 2];
__device__ int   d_cnt   [N_NODESC];
__device__ int   d_rowptr[N_NODESC + 1];
__device__ int   d_cursor[N_NODESC];
__device__ int   d_csr   [NEC];
__device__ int   d_bsumex[NB_SCAN + 1];
__device__ float d_vacc[IN_DIMC];
__device__ float d_vmaxf[2];
__device__ float d_vdenf[2];
__device__ float d_vaggp[VAGG_B][DHIDC];

// ---------------- helpers ----------------
__device__ __forceinline__ float lrelu(float v) { return v > 0.f ? v : 0.2f * v; }
__device__ __forceinline__ float wsum(float v) {
#pragma unroll
    for (int o = 16; o; o >>= 1) v += __shfl_xor_sync(0xffffffffu, v, o);
    return v;
}
__device__ __forceinline__ float wmax(float v) {
#pragma unroll
    for (int o = 16; o; o >>= 1) v = fmaxf(v, __shfl_xor_sync(0xffffffffu, v, o));
    return v;
}
__device__ __forceinline__ void ffma2(unsigned long long& d, unsigned long long a,
                                      unsigned long long b) {
    asm("fma.rn.f32x2 %0, %1, %2, %0;" : "+l"(d) : "l"(a), "l"(b));
}
__device__ __forceinline__ float lo32(unsigned long long v) { return __uint_as_float((unsigned)v); }
__device__ __forceinline__ float hi32(unsigned long long v) { return __uint_as_float((unsigned)(v >> 32)); }

__device__ __forceinline__ void split2(float a, float b, unsigned& hi, unsigned& lo) {
    __nv_bfloat16 ha = __float2bfloat16(a), hb = __float2bfloat16(b);
    __nv_bfloat16 la = __float2bfloat16(a - __bfloat162float(ha));
    __nv_bfloat16 lb = __float2bfloat16(b - __bfloat162float(hb));
    __nv_bfloat162 H = {ha, hb}, L = {la, lb};
    hi = *(unsigned*)&H;  lo = *(unsigned*)&L;
}
__device__ __forceinline__ void cp16(__nv_bfloat16* dst, const __nv_bfloat16* src) {
    uint32_t d = (uint32_t)__cvta_generic_to_shared(dst);
    asm volatile("cp.async.cg.shared.global [%0], [%1], 16;" :: "r"(d), "l"(src));
}

// ---------------- vnode input mean ----------------
__global__ void vacc_zero_k() { d_vacc[threadIdx.x] = 0.f; }
__global__ void vnode_partial_k(const float* __restrict__ X) {
    int t = threadIdx.x;
    float loc = 0.f;
    for (int r = blockIdx.x; r < N_NODESC; r += gridDim.x)
        loc += X[(size_t)r * IN_DIMC + t];
    atomicAdd(&d_vacc[t], loc);
}

// ---------------- conversions ----------------
__global__ void convx0_k(const float* __restrict__ X) {
    size_t i4 = (size_t)blockIdx.x * blockDim.x + threadIdx.x;
    if (i4 >= (size_t)NVC * IN_DIMC / 4) return;
    size_t i = i4 * 4;
    int row = (int)(i / IN_DIMC);
    int k   = (int)(i % IN_DIMC);
    float4 v;
    if (row < N_NODESC) v = *(const float4*)&X[i];
    else {
        const float inv = 1.f / (float)N_NODESC;
        v.x = d_vacc[k] * inv; v.y = d_vacc[k + 1] * inv;
        v.z = d_vacc[k + 2] * inv; v.w = d_vacc[k + 3] * inv;
    }
    uint2 hi, lo;
    split2(v.x, v.y, hi.x, lo.x);
    split2(v.z, v.w, hi.y, lo.y);
    *(uint2*)&d_Ahi[i] = hi;
    *(uint2*)&d_Alo[i] = lo;
}
__global__ void convw_all_k(const float* __restrict__ W0, const float* __restrict__ W1,
                            const float* __restrict__ W2) {
    int idx = blockIdx.x * blockDim.x + threadIdx.x;
    int l, K; const float* W; int base = idx;
    if (base < DHIDC * IN_DIMC)      { l = 0; K = IN_DIMC; W = W0; }
    else if ((base -= DHIDC * IN_DIMC) < DHIDC * HIDC) { l = 1; K = HIDC; W = W1; }
    else if ((base -= DHIDC * HIDC) < DHIDC * HIDC)    { l = 2; K = HIDC; W = W2; }
    else return;
    int n = base / K, k = base % K;
    float v = W[(size_t)k * DHIDC + n];
    __nv_bfloat16 h = __float2bfloat16(v);
    d_Bhi[l][n * K + k] = h;
    d_Blo[l][n * K + k] = __float2bfloat16(v - __bfloat162float(h));
}

// ---------------- CSR build ----------------
__global__ void hist_k(const int* __restrict__ ei) {
    int e = blockIdx.x * blockDim.x + threadIdx.x;
    if (e < NEC) atomicAdd(&d_cnt[ei[NEC + e]], 1);
}
__global__ void scanb_k() {
    __shared__ int bs[NB_SCAN];
    int b = threadIdx.x;
    if (b < NB_SCAN) {
        int s = 0;
        int base = b * 512;
#pragma unroll 8
        for (int i = 0; i < 512; i++) {
            int idx = base + i;
            if (idx < N_NODESC) s += d_cnt[idx];
        }
        bs[b] = s;
    }
    __syncthreads();
    if (threadIdx.x == 0) {
        int carry = 0;
        for (int i = 0; i < NB_SCAN; i++) { d_bsumex[i] = carry; carry += bs[i]; }
        d_bsumex[NB_SCAN] = carry;
    }
}
__global__ void rowptr_k() {
    __shared__ int sh[512];
    int t = threadIdx.x;
    int idx = blockIdx.x * 512 + t;
    int c = (idx < N_NODESC) ? d_cnt[idx] : 0;
    sh[t] = c;
    __syncthreads();
#pragma unroll
    for (int o = 1; o < 512; o <<= 1) {
        int v = (t >= o) ? sh[t - o] : 0;
        __syncthreads();
        sh[t] += v;
        __syncthreads();
    }
    if (idx < N_NODESC) {
        int p = d_bsumex[blockIdx.x] + sh[t] - c;
        d_rowptr[idx] = p;
        d_cursor[idx] = p;
    }
    if (idx == 0) d_rowptr[N_NODESC] = NEC;
}
__global__ void scatter_k(const int* __restrict__ ei) {
    int e = blockIdx.x * blockDim.x + threadIdx.x;
    if (e >= NEC) return;
    int d = ei[NEC + e];
    int p = atomicAdd(&d_cursor[d], 1);
    d_csr[p] = ei[e];
}

// ---------------- wmma bf16 hi/lo GEMM + fused alpha + fp16 H epilogue ----------------
#define SSTR 48
#define ARR_E  (128 * SSTR)
#define BUF_E  (4 * ARR_E)
#define WG_SMEM (2 * BUF_E * 2)      // 98304 B; epilogue reuses 64KB of it

__global__ void __launch_bounds__(256) wgemm_k(const __nv_bfloat16* __restrict__ Bhi,
                                               const __nv_bfloat16* __restrict__ Blo,
                                               int K,
                                               const float* __restrict__ aSv,
                                               const float* __restrict__ aDv) {
    extern __shared__ __align__(128) __nv_bfloat16 sm[];
    const int tid = threadIdx.x;
    const int wid = tid >> 5;
    const int lane = tid & 31;
    const int wm = wid & 3;
    const int wn = wid >> 2;
    const int row0 = blockIdx.y * 128;
    const int col0 = blockIdx.x * 128;   // == head * 128
    const int head = blockIdx.x;

    wmma::fragment<wmma::accumulator, 16, 16, 16, float> acc[2][4];
#pragma unroll
    for (int i = 0; i < 2; i++)
#pragma unroll
        for (int j = 0; j < 4; j++) wmma::fill_fragment(acc[i][j], 0.f);

    const int nch = K >> 5;

    auto issue = [&](int c, int buf) {
        const int k0 = c << 5;
        __nv_bfloat16* base = sm + buf * BUF_E;
#pragma unroll
        for (int s = tid; s < 512; s += 256) {
            int r = s >> 2, q = s & 3;
            size_t ga = (size_t)(row0 + r) * K + k0 + q * 8;
            size_t gb = (size_t)(col0 + r) * K + k0 + q * 8;
            int so = r * SSTR + q * 8;
            cp16(base + so,             &d_Ahi[ga]);
            cp16(base + ARR_E + so,     &d_Alo[ga]);
            cp16(base + 2 * ARR_E + so, &Bhi[gb]);
            cp16(base + 3 * ARR_E + so, &Blo[gb]);
        }
        asm volatile("cp.async.commit_group;");
    };

    issue(0, 0);
    for (int c = 0; c < nch; c++) {
        const int buf = c & 1;
        if (c + 1 < nch) {
            issue(c + 1, buf ^ 1);
            asm volatile("cp.async.wait_group 1;");
        } else {
            asm volatile("cp.async.wait_group 0;");
        }
        __syncthreads();

        const __nv_bfloat16* Ah = sm + buf * BUF_E;
        const __nv_bfloat16* Al = Ah + ARR_E;
        const __nv_bfloat16* Bh = Ah + 2 * ARR_E;
        const __nv_bfloat16* Bl = Ah + 3 * ARR_E;
#pragma unroll
        for (int kk = 0; kk < 32; kk += 16) {
            wmma::fragment<wmma::matrix_a, 16, 16, 16, __nv_bfloat16, wmma::row_major> ah[2], al[2];
#pragma unroll
            for (int i = 0; i < 2; i++) {
                wmma::load_matrix_sync(ah[i], Ah + (wm * 32 + i * 16) * SSTR + kk, SSTR);
                wmma::load_matrix_sync(al[i], Al + (wm * 32 + i * 16) * SSTR + kk, SSTR);
            }
#pragma unroll
            for (int j = 0; j < 4; j++) {
                wmma::fragment<wmma::matrix_b, 16, 16, 16, __nv_bfloat16, wmma::col_major> bh, bl;
                wmma::load_matrix_sync(bh, Bh + (wn * 64 + j * 16) * SSTR + kk, SSTR);
                wmma::load_matrix_sync(bl, Bl + (wn * 64 + j * 16) * SSTR + kk, SSTR);
#pragma unroll
                for (int i = 0; i < 2; i++) {
                    wmma::mma_sync(acc[i][j], ah[i], bh, acc[i][j]);
                    wmma::mma_sync(acc[i][j], ah[i], bl, acc[i][j]);
                    wmma::mma_sync(acc[i][j], al[i], bh, acc[i][j]);
                }
            }
        }
        __syncthreads();
    }

    // ---- epilogue: stage fp32 tile in smem ----
    float* C = (float*)sm;   // 128 x 128 = 64KB
#pragma unroll
    for (int i = 0; i < 2; i++)
#pragma unroll
        for (int j = 0; j < 4; j++)
            wmma::store_matrix_sync(C + (size_t)(wm * 32 + i * 16) * 128 + wn * 64 + j * 16,
                                    acc[i][j], 128, wmma::mem_row_major);
    __syncthreads();

    // fused alpha (fp32): warp wid handles rows wid*16 .. wid*16+15
    float4 sv = *(const float4*)&aSv[col0 + lane * 4];
    float4 dv = *(const float4*)&aDv[col0 + lane * 4];
#pragma unroll
    for (int rr = 0; rr < 16; rr++) {
        int r = wid * 16 + rr;
        float4 cv = *(const float4*)&C[(size_t)r * 128 + lane * 4];
        float sa = cv.x * sv.x + cv.y * sv.y + cv.z * sv.z + cv.w * sv.w;
        float sd = cv.x * dv.x + cv.y * dv.y + cv.z * dv.z + cv.w * dv.w;
        sa = wsum(sa); sd = wsum(sd);
        int row = row0 + r;
        if (lane == 0 && row < NVC) {
            d_As[2 * row + head] = sa;
            d_Ad[2 * row + head] = sd;
        }
    }

    // fp16 H write
    for (int s = tid; s < 128 * 64; s += 256) {
        int r = s >> 6, q = s & 63;
        float2 f = make_float2(C[(size_t)r * 128 + 2 * q], C[(size_t)r * 128 + 2 * q + 1]);
        *(__half2*)&d_Hh[(size_t)(row0 + r) * DHIDC + col0 + 2 * q] = __float22half2_rn(f);
    }
}

// ---------------- vnode chain ----------------
__global__ void vn_pre_k() {
    __shared__ float sm0[1024], sm1[1024];
    int t = threadIdx.x;
    float Ad0 = d_Ad[2 * VN], Ad1 = d_Ad[2 * VN + 1];
    float m0 = -INFINITY, m1 = -INFINITY;
    for (int i = t; i < NVC; i += 1024) {
        m0 = fmaxf(m0, lrelu(d_As[2 * i]     + Ad0));
        m1 = fmaxf(m1, lrelu(d_As[2 * i + 1] + Ad1));
    }
    sm0[t] = m0; sm1[t] = m1;
    __syncthreads();
    for (int o = 512; o; o >>= 1) {
        if (t < o) { sm0[t] = fmaxf(sm0[t], sm0[t + o]); sm1[t] = fmaxf(sm1[t], sm1[t + o]); }
        __syncthreads();
    }
    m0 = sm0[0]; m1 = sm1[0];
    __syncthreads();
    float s0 = 0.f, s1 = 0.f;
    for (int i = t; i < NVC; i += 1024) {
        s0 += expf(lrelu(d_As[2 * i]     + Ad0) - m0);
        s1 += expf(lrelu(d_As[2 * i + 1] + Ad1) - m1);
    }
    sm0[t] = s0; sm1[t] = s1;
    __syncthreads();
    for (int o = 512; o; o >>= 1) {
        if (t < o) { sm0[t] += sm0[t + o]; sm1[t] += sm1[t + o]; }
        __syncthreads();
    }
    if (t == 0) {
        d_vmaxf[0] = m0; d_vmaxf[1] = m1;
        d_vdenf[0] = sm0[0]; d_vdenf[1] = sm1[0];
    }
}
__global__ void vn_agg_k() {
    int t = threadIdx.x;
    int r0 = blockIdx.x * VROWS;
    int r1 = min(r0 + VROWS, NVC);
    float Ad0 = d_Ad[2 * VN], Ad1 = d_Ad[2 * VN + 1];
    float m0 = d_vmaxf[0], m1 = d_vmaxf[1];
    __shared__ float w0sh[256], w1sh[256];
    float acc = 0.f;
    int head = t >> 7;
    for (int base = r0; base < r1; base += 256) {
        int r = base + t;
        if (r < r1) {
            w0sh[t] = expf(lrelu(d_As[2 * r] + Ad0) - m0);
            w1sh[t] = expf(lrelu(d_As[2 * r + 1] + Ad1) - m1);
        }
        __syncthreads();
        int cnt = min(256, r1 - base);
        const float* wsh = head ? w1sh : w0sh;
        for (int j = 0; j < cnt; j++)
            acc += wsh[j] * __half2float(d_Hh[(size_t)(base + j) * DHIDC + t]);
        __syncthreads();
    }
    d_vaggp[blockIdx.x][t] = acc;
}
__global__ void vn_fin_k(const float* __restrict__ b, const float* __restrict__ g,
                         const float* __restrict__ be) {
    int t = threadIdx.x;
    float a0 = 0.f, a1 = 0.f;
    for (int bidx = 0; bidx < VAGG_B; bidx++) {
        a0 += d_vaggp[bidx][t];
        a1 += d_vaggp[bidx][HIDC + t];
    }
    float den0 = d_vdenf[0] + 1e-16f, den1 = d_vdenf[1] + 1e-16f;
    float v = 0.5f * (a0 / den0 + a1 / den1) + b[t];
    __shared__ float sh[HIDC];
    sh[t] = v; __syncthreads();
    for (int o = 64; o; o >>= 1) { if (t < o) sh[t] += sh[t + o]; __syncthreads(); }
    float mu = sh[0] * (1.f / HIDC);
    __syncthreads();
    float dv = v - mu;
    sh[t] = dv * dv; __syncthreads();
    for (int o = 64; o; o >>= 1) { if (t < o) sh[t] += sh[t + o]; __syncthreads(); }
    float var = sh[0] * (1.f / HIDC);
    float y = dv * rsqrtf(var + 1e-5f) * g[t] + be[t];
    float ge = 0.5f * y * (1.f + erff(y * 0.70710678118654752f));
    d_Feat[(size_t)VN * HIDC + t] = ge;
    __nv_bfloat16 h = __float2bfloat16(ge);
    d_Ahi[(size_t)VN * HIDC + t] = h;
    d_Alo[(size_t)VN * HIDC + t] = __float2bfloat16(ge - __bfloat162float(h));
}

// ---------------- node epilogue helpers ----------------
__device__ __forceinline__ void ln_epi(int d, int lane, float ax, float ay, float az, float aw,
                                       const float* __restrict__ b, const float* __restrict__ g,
                                       const float* __restrict__ be) {
    const int c = lane * 4;
    float y0 = ax + b[c], y1 = ay + b[c + 1], y2 = az + b[c + 2], y3 = aw + b[c + 3];
    float mu = wsum(y0 + y1 + y2 + y3) * (1.f / HIDC);
    float d0 = y0 - mu, d1 = y1 - mu, d2 = y2 - mu, d3 = y3 - mu;
    float var = wsum(d0 * d0 + d1 * d1 + d2 * d2 + d3 * d3) * (1.f / HIDC);
    float rs = rsqrtf(var + 1e-5f);
    float z0 = d0 * rs * g[c]     + be[c];
    float z1 = d1 * rs * g[c + 1] + be[c + 1];
    float z2 = d2 * rs * g[c + 2] + be[c + 2];
    float z3 = d3 * rs * g[c + 3] + be[c + 3];
    const float kk = 0.70710678118654752f;
    float4 o;
    o.x = 0.5f * z0 * (1.f + erff(z0 * kk));
    o.y = 0.5f * z1 * (1.f + erff(z1 * kk));
    o.z = 0.5f * z2 * (1.f + erff(z2 * kk));
    o.w = 0.5f * z3 * (1.f + erff(z3 * kk));
    *(float4*)&d_Feat[(size_t)d * HIDC + c] = o;
    uint2 hi, lo;
    split2(o.x, o.y, hi.x, lo.x);
    split2(o.z, o.w, hi.y, lo.y);
    *(uint2*)&d_Ahi[(size_t)d * HIDC + c] = hi;
    *(uint2*)&d_Alo[(size_t)d * HIDC + c] = lo;
}
__device__ __forceinline__ void gather_edge(int s, float w0, float w1, int c,
                                            float& ax, float& ay, float& az, float& aw) {
    uint2 p0 = *(const uint2*)&d_Hh[(size_t)s * DHIDC + c];
    uint2 p1 = *(const uint2*)&d_Hh[(size_t)s * DHIDC + HIDC + c];
    float2 a0 = __half22float2(*(__half2*)&p0.x);
    float2 a1 = __half22float2(*(__half2*)&p0.y);
    float2 b0 = __half22float2(*(__half2*)&p1.x);
    float2 b1 = __half22float2(*(__half2*)&p1.y);
    ax += w0 * a0.x + w1 * b0.x;
    ay += w0 * a0.y + w1 * b0.y;
    az += w0 * a1.x + w1 * b1.x;
    aw += w0 * a1.y + w1 * b1.y;
}

// ---------------- fused per-node softmax+aggregate+bias+LN+GELU ----------------
__global__ void node_k(const float* __restrict__ b, const float* __restrict__ g,
                       const float* __restrict__ be) {
    int gid  = blockIdx.x * blockDim.x + threadIdx.x;
    int d    = gid >> 5;
    int lane = gid & 31;
    if (d >= N_NODESC) return;
    const unsigned FULL = 0xffffffffu;
    float Ad0 = d_Ad[2 * d], Ad1 = d_Ad[2 * d + 1];
    int off = d_rowptr[d], end = d_rowptr[d + 1];
    int deg = end - off;

    float ev0 = lrelu(d_As[2 * VN] + Ad0), ev1 = lrelu(d_As[2 * VN + 1] + Ad1);
    float es0 = lrelu(d_As[2 * d]  + Ad0), es1 = lrelu(d_As[2 * d + 1]  + Ad1);

    float ax = 0.f, ay = 0.f, az = 0.f, aw = 0.f;
    const int c = lane * 4;
    float m0, m1, inv0, inv1;

    if (deg <= 32) {
        int s = 0; float l0 = -INFINITY, l1 = -INFINITY;
        if (lane < deg) {
            s  = d_csr[off + lane];
            l0 = lrelu(d_As[2 * s]     + Ad0);
            l1 = lrelu(d_As[2 * s + 1] + Ad1);
        }
        m0 = wmax(fmaxf(l0, fmaxf(ev0, es0)));
        m1 = wmax(fmaxf(l1, fmaxf(ev1, es1)));
        float e0 = (lane < deg) ? expf(l0 - m0) : 0.f;
        float e1 = (lane < deg) ? expf(l1 - m1) : 0.f;
        float den0 = wsum(e0) + expf(ev0 - m0) + expf(es0 - m0);
        float den1 = wsum(e1) + expf(ev1 - m1) + expf(es1 - m1);
        inv0 = 0.5f / (den0 + 1e-16f);
        inv1 = 0.5f / (den1 + 1e-16f);
        float w0 = e0 * inv0, w1 = e1 * inv1;
        for (int j = 0; j < deg; j++) {
            int   sj  = __shfl_sync(FULL, s,  j);
            float w0j = __shfl_sync(FULL, w0, j);
            float w1j = __shfl_sync(FULL, w1, j);
            gather_edge(sj, w0j, w1j, c, ax, ay, az, aw);
        }
    } else {
        m0 = fmaxf(ev0, es0); m1 = fmaxf(ev1, es1);
        for (int i = off + lane; i < end; i += 32) {
            int s = d_csr[i];
            m0 = fmaxf(m0, lrelu(d_As[2 * s]     + Ad0));
            m1 = fmaxf(m1, lrelu(d_As[2 * s + 1] + Ad1));
        }
        m0 = wmax(m0); m1 = wmax(m1);
        float den0 = 0.f, den1 = 0.f;
        for (int i = off + lane; i < end; i += 32) {
            int s = d_csr[i];
            den0 += expf(lrelu(d_As[2 * s]     + Ad0) - m0);
            den1 += expf(lrelu(d_As[2 * s + 1] + Ad1) - m1);
        }
        den0 = wsum(den0) + expf(ev0 - m0) + expf(es0 - m0);
        den1 = wsum(den1) + expf(ev1 - m1) + expf(es1 - m1);
        inv0 = 0.5f / (den0 + 1e-16f);
        inv1 = 0.5f / (den1 + 1e-16f);
        for (int base = off; base < end; base += 32) {
            int n = min(32, end - base);
            int s = 0; float w0 = 0.f, w1 = 0.f;
            if (lane < n) {
                s  = d_csr[base + lane];
                w0 = expf(lrelu(d_As[2 * s]     + Ad0) - m0) * inv0;
                w1 = expf(lrelu(d_As[2 * s + 1] + Ad1) - m1) * inv1;
            }
            for (int j = 0; j < n; j++) {
                int   sj  = __shfl_sync(FULL, s,  j);
                float w0j = __shfl_sync(FULL, w0, j);
                float w1j = __shfl_sync(FULL, w1, j);
                gather_edge(sj, w0j, w1j, c, ax, ay, az, aw);
            }
        }
    }
    gather_edge(VN, expf(ev0 - m0) * inv0, expf(ev1 - m1) * inv1, c, ax, ay, az, aw);
    gather_edge(d,  expf(es0 - m0) * inv0, expf(es1 - m1) * inv1, c, ax, ay, az, aw);

    ln_epi(d, lane, ax, ay, az, aw, b, g, be);
}

// ---------------- fp32 f32x2 GEMM (final projection) ----------------
template<int BN>
__global__ void sgemm_k(const float* __restrict__ A, const float* __restrict__ B,
                        const float* __restrict__ bias, float* __restrict__ C,
                        int M, int K, int N) {
    constexpr int BM = 128, BK = 16, TPB = 2 * BN, GRP = BN / 8;
    __shared__ __align__(16) float2 As2[BK][BM];
    __shared__ __align__(16) float  Bs [BK][BN];
    const int tid = threadIdx.x;
    const int tn = tid % GRP, tm = tid / GRP;
    const int row0 = blockIdx.y * BM, col0 = blockIdx.x * BN;
    unsigned long long acc[8][4];
#pragma unroll
    for (int i = 0; i < 8; i++)
#pragma unroll
        for (int j = 0; j < 4; j++) acc[i][j] = 0ull;
    for (int k0 = 0; k0 < K; k0 += BK) {
        __syncthreads();
#pragma unroll
        for (int s = tid; s < BM * 4; s += TPB) {
            int r = s >> 2, q = s & 3;
            int row = row0 + r;
            float4 v = (row < M) ? *(const float4*)&A[(size_t)row * K + k0 + q * 4]
                                 : make_float4(0.f, 0.f, 0.f, 0.f);
            As2[q * 4 + 0][r] = make_float2(v.x, v.x);
            As2[q * 4 + 1][r] = make_float2(v.y, v.y);
            As2[q * 4 + 2][r] = make_float2(v.z, v.z);
            As2[q * 4 + 3][r] = make_float2(v.w, v.w);
        }
#pragma unroll
        for (int s = tid; s < BK * BN / 4; s += TPB) {
            int br = s / (BN / 4), bc = s % (BN / 4);
            *(float4*)&Bs[br][bc * 4] =
                *(const float4*)&B[(size_t)(k0 + br) * N + col0 + bc * 4];
        }
        __syncthreads();
#pragma unroll
        for (int kk = 0; kk < BK; kk++) {
            unsigned long long a[8], bb[4];
            const ulonglong2* ap = (const ulonglong2*)&As2[kk][tm * 8];
            ulonglong2 a01 = ap[0], a23 = ap[1], a45 = ap[2], a67 = ap[3];
            a[0] = a01.x; a[1] = a01.y; a[2] = a23.x; a[3] = a23.y;
            a[4] = a45.x; a[5] = a45.y; a[6] = a67.x; a[7] = a67.y;
            const ulonglong2* bp = (const ulonglong2*)&Bs[kk][tn * 8];
            ulonglong2 b01 = bp[0], b23 = bp[1];
            bb[0] = b01.x; bb[1] = b01.y; bb[2] = b23.x; bb[3] = b23.y;
#pragma unroll
            for (int i = 0; i < 8; i++)
#pragma unroll
                for (int j = 0; j < 4; j++) ffma2(acc[i][j], a[i], bb[j]);
        }
    }
    float bv[8];
#pragma unroll
    for (int j = 0; j < 8; j++) bv[j] = bias ? bias[col0 + tn * 8 + j] : 0.f;
#pragma unroll
    for (int i = 0; i < 8; i++) {
        int row = row0 + tm * 8 + i;
        if (row < M) {
            float4 o0, o1;
            o0.x = lo32(acc[i][0]) + bv[0]; o0.y = hi32(acc[i][0]) + bv[1];
            o0.z = lo32(acc[i][1]) + bv[2]; o0.w = hi32(acc[i][1]) + bv[3];
            o1.x = lo32(acc[i][2]) + bv[4]; o1.y = hi32(acc[i][2]) + bv[5];
            o1.z = lo32(acc[i][3]) + bv[6]; o1.w = hi32(acc[i][3]) + bv[7];
            *(float4*)&C[(size_t)row * N + col0 + tn * 8]     = o0;
            *(float4*)&C[(size_t)row * N + col0 + tn * 8 + 4] = o1;
        }
    }
}

// ---------------- host launch ----------------
extern "C" void kernel_launch(void* const* d_in, const int* in_sizes, int n_in,
                              void* d_out, int out_size) {
    (void)in_sizes; (void)n_in; (void)out_size;
    const float* X  = (const float*)d_in[0];
    const int*   ei = (const int*)  d_in[1];
    const float* W[3]  = {(const float*)d_in[3],  (const float*)d_in[9],  (const float*)d_in[15]};
    const float* aS[3] = {(const float*)d_in[4],  (const float*)d_in[10], (const float*)d_in[16]};
    const float* aD[3] = {(const float*)d_in[5],  (const float*)d_in[11], (const float*)d_in[17]};
    const float* bb[3] = {(const float*)d_in[6],  (const float*)d_in[12], (const float*)d_in[18]};
    const float* gg[3] = {(const float*)d_in[7],  (const float*)d_in[13], (const float*)d_in[19]};
    const float* bE[3] = {(const float*)d_in[8],  (const float*)d_in[14], (const float*)d_in[20]};
    const float* Wout  = (const float*)d_in[21];
    const float* bout  = (const float*)d_in[22];
    float* out = (float*)d_out;

    float* dFeat; cudaGetSymbolAddress((void**)&dFeat, d_Feat);
    int* dCnt;    cudaGetSymbolAddress((void**)&dCnt, d_cnt);
    __nv_bfloat16 *dBhi, *dBlo;
    cudaGetSymbolAddress((void**)&dBhi, d_Bhi);
    cudaGetSymbolAddress((void**)&dBlo, d_Blo);

    static cudaStream_t sB = nullptr, sC = nullptr;
    static cudaEvent_t evF = nullptr, evJ = nullptr, evC0 = nullptr, evCJ = nullptr;
    if (!sB) {
        cudaStreamCreateWithFlags(&sB, cudaStreamNonBlocking);
        cudaStreamCreateWithFlags(&sC, cudaStreamNonBlocking);
        cudaEventCreateWithFlags(&evF,  cudaEventDisableTiming);
        cudaEventCreateWithFlags(&evJ,  cudaEventDisableTiming);
        cudaEventCreateWithFlags(&evC0, cudaEventDisableTiming);
        cudaEventCreateWithFlags(&evCJ, cudaEventDisableTiming);
        cudaFuncSetAttribute(wgemm_k, cudaFuncAttributeMaxDynamicSharedMemorySize, WG_SMEM);
    }

    // --- fork CSR build onto sC ---
    cudaEventRecord(evC0, 0);
    cudaStreamWaitEvent(sC, evC0, 0);
    cudaMemsetAsync(dCnt, 0, N_NODESC * sizeof(int), sC);
    const int eb = (NEC + 255) / 256;
    hist_k<<<eb, 256, 0, sC>>>(ei);
    scanb_k<<<1, 128, 0, sC>>>();
    rowptr_k<<<NB_SCAN, 512, 0, sC>>>();
    scatter_k<<<eb, 256, 0, sC>>>(ei);
    cudaEventRecord(evCJ, sC);

    // --- main stream ---
    const int wtot = DHIDC * IN_DIMC + 2 * DHIDC * HIDC;
    convw_all_k<<<(wtot + 255) / 256, 256>>>(W[0], W[1], W[2]);
    vacc_zero_k<<<1, IN_DIMC>>>();
    vnode_partial_k<<<512, IN_DIMC>>>(X);
    convx0_k<<<(int)(((size_t)NVC * IN_DIMC / 4 + 255) / 256), 256>>>(X);

    const int node_blocks = (N_NODESC * 32 + 255) / 256;

    for (int l = 0; l < 3; l++) {
        int K = (l == 0) ? IN_DIMC : HIDC;
        dim3 grid(DHIDC / 128, MTILES);
        wgemm_k<<<grid, 256, WG_SMEM>>>(dBhi + (size_t)l * DHIDC * IN_DIMC,
                                        dBlo + (size_t)l * DHIDC * IN_DIMC, K,
                                        aS[l], aD[l]);

        // fork: vnode chain on sB || node_k on main
        cudaEventRecord(evF, 0);
        cudaStreamWaitEvent(sB, evF, 0);
        vn_pre_k<<<1, 1024, 0, sB>>>();
        vn_agg_k<<<VAGG_B, 256, 0, sB>>>();
        vn_fin_k<<<1, HIDC, 0, sB>>>(bb[l], gg[l], bE[l]);

        if (l == 0) cudaStreamWaitEvent(0, evCJ, 0);
        node_k<<<node_blocks, 256>>>(bb[l], gg[l], bE[l]);

        cudaEventRecord(evJ, sB);
        cudaStreamWaitEvent(0, evJ, 0);
    }

    dim3 gridF(1, (N_NODESC + 127) / 128);
    sgemm_k<64><<<gridF, 128>>>(dFeat, Wout, bout, out, N_NODESC, HIDC, OUT_DIMC);
}

// round 13
// speedup vs baseline: 1.6620x; 1.0318x over previous
#include <cuda_runtime.h>
#include <cuda_bf16.h>
#include <cuda_fp16.h>
#include <mma.h>
#include <math.h>
#include <stdint.h>

using namespace nvcuda;

// ---------------- problem constants ----------------
#define N_NODESC 50000
#define NVC      50001
#define NPAD     50048
#define VN       N_NODESC
#define NEC      400000
#define IN_DIMC  256
#define HIDC     128
#define DHIDC    256
#define OUT_DIMC 64
#define NB_SCAN  98
#define VROWS    391
#define MTILES   391
#define VAGG_B   128

// ---------------- scratch ----------------
__device__ __align__(16) __half d_Hh  [(size_t)NPAD * DHIDC];
__device__ __align__(16) float d_Feat[(size_t)NVC * HIDC];
__device__ __align__(16) __nv_bfloat16 d_Ahi[(size_t)NPAD * IN_DIMC];
__device__ __align__(16) __nv_bfloat16 d_Alo[(size_t)NPAD * IN_DIMC];
__device__ __align__(16) __nv_bfloat16 d_Bhi[3][DHIDC * IN_DIMC];
__device__ __align__(16) __nv_bfloat16 d_Blo[3][DHIDC * IN_DIMC];
__device__ __align__(16) __nv_bfloat16 d_BOhi[OUT_DIMC * HIDC];
__device__ __align__(16) __nv_bfloat16 d_BOlo[OUT_DIMC * HIDC];
__device__ float d_As[NPAD * 2];
__device__ float d_Ad[NPAD * 2];
__device__ int   d_cnt   [N_NODESC];
__device__ int   d_rowptr[N_NODESC + 1];
__device__ int   d_cursor[N_NODESC];
__device__ int   d_csr   [NEC];
__device__ int   d_bsumex[NB_SCAN + 1];
__device__ float d_vacc[IN_DIMC];
__device__ float d_vmaxf[2];
__device__ float d_vdenf[2];
__device__ float d_vaggp[VAGG_B][DHIDC];

// ---------------- helpers ----------------
__device__ __forceinline__ float lrelu(float v) { return v > 0.f ? v : 0.2f * v; }
__device__ __forceinline__ float wsum(float v) {
#pragma unroll
    for (int o = 16; o; o >>= 1) v += __shfl_xor_sync(0xffffffffu, v, o);
    return v;
}
__device__ __forceinline__ float wmax(float v) {
#pragma unroll
    for (int o = 16; o; o >>= 1) v = fmaxf(v, __shfl_xor_sync(0xffffffffu, v, o));
    return v;
}
__device__ __forceinline__ void split2(float a, float b, unsigned& hi, unsigned& lo) {
    __nv_bfloat16 ha = __float2bfloat16(a), hb = __float2bfloat16(b);
    __nv_bfloat16 la = __float2bfloat16(a - __bfloat162float(ha));
    __nv_bfloat16 lb = __float2bfloat16(b - __bfloat162float(hb));
    __nv_bfloat162 H = {ha, hb}, L = {la, lb};
    hi = *(unsigned*)&H;  lo = *(unsigned*)&L;
}
__device__ __forceinline__ void cp16(__nv_bfloat16* dst, const __nv_bfloat16* src) {
    uint32_t d = (uint32_t)__cvta_generic_to_shared(dst);
    asm volatile("cp.async.cg.shared.global [%0], [%1], 16;" :: "r"(d), "l"(src));
}

// ---------------- vnode input mean ----------------
__global__ void vacc_zero_k() { d_vacc[threadIdx.x] = 0.f; }
__global__ void vnode_partial_k(const float* __restrict__ X) {
    int t = threadIdx.x;
    float loc = 0.f;
    for (int r = blockIdx.x; r < N_NODESC; r += gridDim.x)
        loc += X[(size_t)r * IN_DIMC + t];
    atomicAdd(&d_vacc[t], loc);
}

// ---------------- conversions ----------------
__global__ void convx0_k(const float* __restrict__ X) {
    size_t i4 = (size_t)blockIdx.x * blockDim.x + threadIdx.x;
    if (i4 >= (size_t)NVC * IN_DIMC / 4) return;
    size_t i = i4 * 4;
    int row = (int)(i / IN_DIMC);
    int k   = (int)(i % IN_DIMC);
    float4 v;
    if (row < N_NODESC) v = *(const float4*)&X[i];
    else {
        const float inv = 1.f / (float)N_NODESC;
        v.x = d_vacc[k] * inv; v.y = d_vacc[k + 1] * inv;
        v.z = d_vacc[k + 2] * inv; v.w = d_vacc[k + 3] * inv;
    }
    uint2 hi, lo;
    split2(v.x, v.y, hi.x, lo.x);
    split2(v.z, v.w, hi.y, lo.y);
    *(uint2*)&d_Ahi[i] = hi;
    *(uint2*)&d_Alo[i] = lo;
}
// all layer weights + Wout, one launch; n-major (k fastest)
__global__ void convw_all_k(const float* __restrict__ W0, const float* __restrict__ W1,
                            const float* __restrict__ W2, const float* __restrict__ Wout) {
    int idx = blockIdx.x * blockDim.x + threadIdx.x;
    int base = idx;
    if (base < DHIDC * IN_DIMC) {
        int n = base / IN_DIMC, k = base % IN_DIMC;
        float v = W0[(size_t)k * DHIDC + n];
        __nv_bfloat16 h = __float2bfloat16(v);
        d_Bhi[0][base] = h;
        d_Blo[0][base] = __float2bfloat16(v - __bfloat162float(h));
        return;
    }
    base -= DHIDC * IN_DIMC;
    if (base < DHIDC * HIDC) {
        int n = base / HIDC, k = base % HIDC;
        float v = W1[(size_t)k * DHIDC + n];
        __nv_bfloat16 h = __float2bfloat16(v);
        d_Bhi[1][base] = h;
        d_Blo[1][base] = __float2bfloat16(v - __bfloat162float(h));
        return;
    }
    base -= DHIDC * HIDC;
    if (base < DHIDC * HIDC) {
        int n = base / HIDC, k = base % HIDC;
        float v = W2[(size_t)k * DHIDC + n];
        __nv_bfloat16 h = __float2bfloat16(v);
        d_Bhi[2][base] = h;
        d_Blo[2][base] = __float2bfloat16(v - __bfloat162float(h));
        return;
    }
    base -= DHIDC * HIDC;
    if (base < OUT_DIMC * HIDC) {
        int n = base / HIDC, k = base % HIDC;
        float v = Wout[(size_t)k * OUT_DIMC + n];
        __nv_bfloat16 h = __float2bfloat16(v);
        d_BOhi[base] = h;
        d_BOlo[base] = __float2bfloat16(v - __bfloat162float(h));
    }
}

// ---------------- CSR build ----------------
__global__ void hist_k(const int* __restrict__ ei) {
    int e = blockIdx.x * blockDim.x + threadIdx.x;
    if (e < NEC) atomicAdd(&d_cnt[ei[NEC + e]], 1);
}
__global__ void scanb_k() {
    __shared__ int bs[NB_SCAN];
    int b = threadIdx.x;
    if (b < NB_SCAN) {
        int s = 0;
        int base = b * 512;
#pragma unroll 8
        for (int i = 0; i < 512; i++) {
            int idx = base + i;
            if (idx < N_NODESC) s += d_cnt[idx];
        }
        bs[b] = s;
    }
    __syncthreads();
    if (threadIdx.x == 0) {
        int carry = 0;
        for (int i = 0; i < NB_SCAN; i++) { d_bsumex[i] = carry; carry += bs[i]; }
        d_bsumex[NB_SCAN] = carry;
    }
}
__global__ void rowptr_k() {
    __shared__ int sh[512];
    int t = threadIdx.x;
    int idx = blockIdx.x * 512 + t;
    int c = (idx < N_NODESC) ? d_cnt[idx] : 0;
    sh[t] = c;
    __syncthreads();
#pragma unroll
    for (int o = 1; o < 512; o <<= 1) {
        int v = (t >= o) ? sh[t - o] : 0;
        __syncthreads();
        sh[t] += v;
        __syncthreads();
    }
    if (idx < N_NODESC) {
        int p = d_bsumex[blockIdx.x] + sh[t] - c;
        d_rowptr[idx] = p;
        d_cursor[idx] = p;
    }
    if (idx == 0) d_rowptr[N_NODESC] = NEC;
}
__global__ void scatter_k(const int* __restrict__ ei) {
    int e = blockIdx.x * blockDim.x + threadIdx.x;
    if (e >= NEC) return;
    int d = ei[NEC + e];
    int p = atomicAdd(&d_cursor[d], 1);
    d_csr[p] = ei[e];
}

// ---------------- wmma bf16 hi/lo GEMM + fused alpha + fp16 H epilogue ----------------
#define SSTR 48
#define ARR_E  (128 * SSTR)
#define BUF_E  (4 * ARR_E)
#define WG_SMEM (2 * BUF_E * 2)      // 98304

__global__ void __launch_bounds__(256) wgemm_k(const __nv_bfloat16* __restrict__ Bhi,
                                               const __nv_bfloat16* __restrict__ Blo,
                                               int K,
                                               const float* __restrict__ aSv,
                                               const float* __restrict__ aDv) {
    extern __shared__ __align__(128) __nv_bfloat16 sm[];
    const int tid = threadIdx.x;
    const int wid = tid >> 5;
    const int lane = tid & 31;
    const int wm = wid & 3;
    const int wn = wid >> 2;
    const int row0 = blockIdx.y * 128;
    const int col0 = blockIdx.x * 128;
    const int head = blockIdx.x;

    wmma::fragment<wmma::accumulator, 16, 16, 16, float> acc[2][4];
#pragma unroll
    for (int i = 0; i < 2; i++)
#pragma unroll
        for (int j = 0; j < 4; j++) wmma::fill_fragment(acc[i][j], 0.f);

    const int nch = K >> 5;

    auto issue = [&](int c, int buf) {
        const int k0 = c << 5;
        __nv_bfloat16* base = sm + buf * BUF_E;
#pragma unroll
        for (int s = tid; s < 512; s += 256) {
            int r = s >> 2, q = s & 3;
            size_t ga = (size_t)(row0 + r) * K + k0 + q * 8;
            size_t gb = (size_t)(col0 + r) * K + k0 + q * 8;
            int so = r * SSTR + q * 8;
            cp16(base + so,             &d_Ahi[ga]);
            cp16(base + ARR_E + so,     &d_Alo[ga]);
            cp16(base + 2 * ARR_E + so, &Bhi[gb]);
            cp16(base + 3 * ARR_E + so, &Blo[gb]);
        }
        asm volatile("cp.async.commit_group;");
    };

    issue(0, 0);
    for (int c = 0; c < nch; c++) {
        const int buf = c & 1;
        if (c + 1 < nch) {
            issue(c + 1, buf ^ 1);
            asm volatile("cp.async.wait_group 1;");
        } else {
            asm volatile("cp.async.wait_group 0;");
        }
        __syncthreads();

        const __nv_bfloat16* Ah = sm + buf * BUF_E;
        const __nv_bfloat16* Al = Ah + ARR_E;
        const __nv_bfloat16* Bh = Ah + 2 * ARR_E;
        const __nv_bfloat16* Bl = Ah + 3 * ARR_E;
#pragma unroll
        for (int kk = 0; kk < 32; kk += 16) {
            wmma::fragment<wmma::matrix_a, 16, 16, 16, __nv_bfloat16, wmma::row_major> ah[2], al[2];
#pragma unroll
            for (int i = 0; i < 2; i++) {
                wmma::load_matrix_sync(ah[i], Ah + (wm * 32 + i * 16) * SSTR + kk, SSTR);
                wmma::load_matrix_sync(al[i], Al + (wm * 32 + i * 16) * SSTR + kk, SSTR);
            }
#pragma unroll
            for (int j = 0; j < 4; j++) {
                wmma::fragment<wmma::matrix_b, 16, 16, 16, __nv_bfloat16, wmma::col_major> bh, bl;
                wmma::load_matrix_sync(bh, Bh + (wn * 64 + j * 16) * SSTR + kk, SSTR);
                wmma::load_matrix_sync(bl, Bl + (wn * 64 + j * 16) * SSTR + kk, SSTR);
#pragma unroll
                for (int i = 0; i < 2; i++) {
                    wmma::mma_sync(acc[i][j], ah[i], bh, acc[i][j]);
                    wmma::mma_sync(acc[i][j], ah[i], bl, acc[i][j]);
                    wmma::mma_sync(acc[i][j], al[i], bh, acc[i][j]);
                }
            }
        }
        __syncthreads();
    }

    // ---- epilogue: stage fp32 tile in smem ----
    float* C = (float*)sm;   // 64KB
#pragma unroll
    for (int i = 0; i < 2; i++)
#pragma unroll
        for (int j = 0; j < 4; j++)
            wmma::store_matrix_sync(C + (size_t)(wm * 32 + i * 16) * 128 + wn * 64 + j * 16,
                                    acc[i][j], 128, wmma::mem_row_major);
    __syncthreads();

    float4 sv = *(const float4*)&aSv[col0 + lane * 4];
    float4 dv = *(const float4*)&aDv[col0 + lane * 4];
#pragma unroll
    for (int rr = 0; rr < 16; rr++) {
        int r = wid * 16 + rr;
        float4 cv = *(const float4*)&C[(size_t)r * 128 + lane * 4];
        float sa = cv.x * sv.x + cv.y * sv.y + cv.z * sv.z + cv.w * sv.w;
        float sd = cv.x * dv.x + cv.y * dv.y + cv.z * dv.z + cv.w * dv.w;
        sa = wsum(sa); sd = wsum(sd);
        int row = row0 + r;
        if (lane == 0 && row < NVC) {
            d_As[2 * row + head] = sa;
            d_Ad[2 * row + head] = sd;
        }
    }

    for (int s = tid; s < 128 * 64; s += 256) {
        int r = s >> 6, q = s & 63;
        float2 f = make_float2(C[(size_t)r * 128 + 2 * q], C[(size_t)r * 128 + 2 * q + 1]);
        *(__half2*)&d_Hh[(size_t)(row0 + r) * DHIDC + col0 + 2 * q] = __float22half2_rn(f);
    }
}

// ---------------- final projection: bf16 hi/lo wmma, 128x64 tile ----------------
#define ARRB_E (64 * SSTR)
#define BUFF_E (2 * ARR_E + 2 * ARRB_E)      // 18432 elems
#define WGF_SMEM (2 * BUFF_E * 2)            // 73728 B

__global__ void __launch_bounds__(256) wgemmF_k(const float* __restrict__ bias,
                                                float* __restrict__ out) {
    extern __shared__ __align__(128) __nv_bfloat16 sm[];
    const int tid = threadIdx.x;
    const int wid = tid >> 5;             // 8 warps, 16 rows each
    const int row0 = blockIdx.x * 128;
    const int K = HIDC;

    wmma::fragment<wmma::accumulator, 16, 16, 16, float> acc[4];
#pragma unroll
    for (int j = 0; j < 4; j++) wmma::fill_fragment(acc[j], 0.f);

    const int nch = K >> 5;   // 4

    auto issue = [&](int c, int buf) {
        const int k0 = c << 5;
        __nv_bfloat16* base = sm + buf * BUFF_E;
#pragma unroll
        for (int s = tid; s < 512; s += 256) {
            int r = s >> 2, q = s & 3;
            size_t ga = (size_t)(row0 + r) * K + k0 + q * 8;
            int so = r * SSTR + q * 8;
            cp16(base + so,         &d_Ahi[ga]);
            cp16(base + ARR_E + so, &d_Alo[ga]);
        }
        for (int s = tid; s < 256; s += 256) {
            int r = s >> 2, q = s & 3;
            size_t gb = (size_t)r * K + k0 + q * 8;
            int so = r * SSTR + q * 8;
            cp16(base + 2 * ARR_E + so,          &d_BOhi[gb]);
            cp16(base + 2 * ARR_E + ARRB_E + so, &d_BOlo[gb]);
        }
        asm volatile("cp.async.commit_group;");
    };

    issue(0, 0);
    for (int c = 0; c < nch; c++) {
        const int buf = c & 1;
        if (c + 1 < nch) {
            issue(c + 1, buf ^ 1);
            asm volatile("cp.async.wait_group 1;");
        } else {
            asm volatile("cp.async.wait_group 0;");
        }
        __syncthreads();

        const __nv_bfloat16* Ah = sm + buf * BUFF_E;
        const __nv_bfloat16* Al = Ah + ARR_E;
        const __nv_bfloat16* Bh = Ah + 2 * ARR_E;
        const __nv_bfloat16* Bl = Bh + ARRB_E;
#pragma unroll
        for (int kk = 0; kk < 32; kk += 16) {
            wmma::fragment<wmma::matrix_a, 16, 16, 16, __nv_bfloat16, wmma::row_major> ah, al;
            wmma::load_matrix_sync(ah, Ah + (wid * 16) * SSTR + kk, SSTR);
            wmma::load_matrix_sync(al, Al + (wid * 16) * SSTR + kk, SSTR);
#pragma unroll
            for (int j = 0; j < 4; j++) {
                wmma::fragment<wmma::matrix_b, 16, 16, 16, __nv_bfloat16, wmma::col_major> bh, bl;
                wmma::load_matrix_sync(bh, Bh + (j * 16) * SSTR + kk, SSTR);
                wmma::load_matrix_sync(bl, Bl + (j * 16) * SSTR + kk, SSTR);
                wmma::mma_sync(acc[j], ah, bh, acc[j]);
                wmma::mma_sync(acc[j], ah, bl, acc[j]);
                wmma::mma_sync(acc[j], al, bh, acc[j]);
            }
        }
        __syncthreads();
    }

    float* C = (float*)sm;   // 128 x 64 fp32 = 32KB
#pragma unroll
    for (int j = 0; j < 4; j++)
        wmma::store_matrix_sync(C + (size_t)(wid * 16) * OUT_DIMC + j * 16,
                                acc[j], OUT_DIMC, wmma::mem_row_major);
    __syncthreads();

    for (int s = tid; s < 128 * (OUT_DIMC / 4); s += 256) {
        int r = s / (OUT_DIMC / 4), q = s % (OUT_DIMC / 4);
        int row = row0 + r;
        if (row < N_NODESC) {
            float4 v = *(const float4*)&C[(size_t)r * OUT_DIMC + q * 4];
            float4 bv = *(const float4*)&bias[q * 4];
            v.x += bv.x; v.y += bv.y; v.z += bv.z; v.w += bv.w;
            *(float4*)&out[(size_t)row * OUT_DIMC + q * 4] = v;
        }
    }
}

// ---------------- vnode chain ----------------
__global__ void vn_pre_k() {
    __shared__ float sm0[1024], sm1[1024];
    int t = threadIdx.x;
    float Ad0 = d_Ad[2 * VN], Ad1 = d_Ad[2 * VN + 1];
    float m0 = -INFINITY, m1 = -INFINITY;
    for (int i = t; i < NVC; i += 1024) {
        m0 = fmaxf(m0, lrelu(d_As[2 * i]     + Ad0));
        m1 = fmaxf(m1, lrelu(d_As[2 * i + 1] + Ad1));
    }
    sm0[t] = m0; sm1[t] = m1;
    __syncthreads();
    for (int o = 512; o; o >>= 1) {
        if (t < o) { sm0[t] = fmaxf(sm0[t], sm0[t + o]); sm1[t] = fmaxf(sm1[t], sm1[t + o]); }
        __syncthreads();
    }
    m0 = sm0[0]; m1 = sm1[0];
    __syncthreads();
    float s0 = 0.f, s1 = 0.f;
    for (int i = t; i < NVC; i += 1024) {
        s0 += __expf(lrelu(d_As[2 * i]     + Ad0) - m0);
        s1 += __expf(lrelu(d_As[2 * i + 1] + Ad1) - m1);
    }
    sm0[t] = s0; sm1[t] = s1;
    __syncthreads();
    for (int o = 512; o; o >>= 1) {
        if (t < o) { sm0[t] += sm0[t + o]; sm1[t] += sm1[t + o]; }
        __syncthreads();
    }
    if (t == 0) {
        d_vmaxf[0] = m0; d_vmaxf[1] = m1;
        d_vdenf[0] = sm0[0]; d_vdenf[1] = sm1[0];
    }
}
__global__ void vn_agg_k() {
    int t = threadIdx.x;
    int r0 = blockIdx.x * VROWS;
    int r1 = min(r0 + VROWS, NVC);
    float Ad0 = d_Ad[2 * VN], Ad1 = d_Ad[2 * VN + 1];
    float m0 = d_vmaxf[0], m1 = d_vmaxf[1];
    __shared__ float w0sh[256], w1sh[256];
    float acc = 0.f;
    int head = t >> 7;
    for (int base = r0; base < r1; base += 256) {
        int r = base + t;
        if (r < r1) {
            w0sh[t] = __expf(lrelu(d_As[2 * r] + Ad0) - m0);
            w1sh[t] = __expf(lrelu(d_As[2 * r + 1] + Ad1) - m1);
        }
        __syncthreads();
        int cnt = min(256, r1 - base);
        const float* wsh = head ? w1sh : w0sh;
        for (int j = 0; j < cnt; j++)
            acc += wsh[j] * __half2float(d_Hh[(size_t)(base + j) * DHIDC + t]);
        __syncthreads();
    }
    d_vaggp[blockIdx.x][t] = acc;
}
__global__ void vn_fin_k(const float* __restrict__ b, const float* __restrict__ g,
                         const float* __restrict__ be) {
    int t = threadIdx.x;
    float a0 = 0.f, a1 = 0.f;
    for (int bidx = 0; bidx < VAGG_B; bidx++) {
        a0 += d_vaggp[bidx][t];
        a1 += d_vaggp[bidx][HIDC + t];
    }
    float den0 = d_vdenf[0] + 1e-16f, den1 = d_vdenf[1] + 1e-16f;
    float v = 0.5f * (a0 / den0 + a1 / den1) + b[t];
    __shared__ float sh[HIDC];
    sh[t] = v; __syncthreads();
    for (int o = 64; o; o >>= 1) { if (t < o) sh[t] += sh[t + o]; __syncthreads(); }
    float mu = sh[0] * (1.f / HIDC);
    __syncthreads();
    float dv = v - mu;
    sh[t] = dv * dv; __syncthreads();
    for (int o = 64; o; o >>= 1) { if (t < o) sh[t] += sh[t + o]; __syncthreads(); }
    float var = sh[0] * (1.f / HIDC);
    float y = dv * rsqrtf(var + 1e-5f) * g[t] + be[t];
    float ge = 0.5f * y * (1.f + erff(y * 0.70710678118654752f));
    d_Feat[(size_t)VN * HIDC + t] = ge;
    __nv_bfloat16 h = __float2bfloat16(ge);
    d_Ahi[(size_t)VN * HIDC + t] = h;
    d_Alo[(size_t)VN * HIDC + t] = __float2bfloat16(ge - __bfloat162float(h));
}

// ---------------- node epilogue helpers ----------------
__device__ __forceinline__ void ln_epi(int d, int lane, float ax, float ay, float az, float aw,
                                       const float* __restrict__ b, const float* __restrict__ g,
                                       const float* __restrict__ be) {
    const int c = lane * 4;
    float y0 = ax + b[c], y1 = ay + b[c + 1], y2 = az + b[c + 2], y3 = aw + b[c + 3];
    float mu = wsum(y0 + y1 + y2 + y3) * (1.f / HIDC);
    float d0 = y0 - mu, d1 = y1 - mu, d2 = y2 - mu, d3 = y3 - mu;
    float var = wsum(d0 * d0 + d1 * d1 + d2 * d2 + d3 * d3) * (1.f / HIDC);
    float rs = rsqrtf(var + 1e-5f);
    float z0 = d0 * rs * g[c]     + be[c];
    float z1 = d1 * rs * g[c + 1] + be[c + 1];
    float z2 = d2 * rs * g[c + 2] + be[c + 2];
    float z3 = d3 * rs * g[c + 3] + be[c + 3];
    const float kk = 0.70710678118654752f;
    float4 o;
    o.x = 0.5f * z0 * (1.f + erff(z0 * kk));
    o.y = 0.5f * z1 * (1.f + erff(z1 * kk));
    o.z = 0.5f * z2 * (1.f + erff(z2 * kk));
    o.w = 0.5f * z3 * (1.f + erff(z3 * kk));
    *(float4*)&d_Feat[(size_t)d * HIDC + c] = o;
    uint2 hi, lo;
    split2(o.x, o.y, hi.x, lo.x);
    split2(o.z, o.w, hi.y, lo.y);
    *(uint2*)&d_Ahi[(size_t)d * HIDC + c] = hi;
    *(uint2*)&d_Alo[(size_t)d * HIDC + c] = lo;
}
__device__ __forceinline__ void gather_edge(int s, float w0, float w1, int c,
                                            float& ax, float& ay, float& az, float& aw) {
    uint2 p0 = *(const uint2*)&d_Hh[(size_t)s * DHIDC + c];
    uint2 p1 = *(const uint2*)&d_Hh[(size_t)s * DHIDC + HIDC + c];
    float2 a0 = __half22float2(*(__half2*)&p0.x);
    float2 a1 = __half22float2(*(__half2*)&p0.y);
    float2 b0 = __half22float2(*(__half2*)&p1.x);
    float2 b1 = __half22float2(*(__half2*)&p1.y);
    ax += w0 * a0.x + w1 * b0.x;
    ay += w0 * a0.y + w1 * b0.y;
    az += w0 * a1.x + w1 * b1.x;
    aw += w0 * a1.y + w1 * b1.y;
}

// ---------------- fused per-node softmax+aggregate+bias+LN+GELU ----------------
__global__ void node_k(const float* __restrict__ b, const float* __restrict__ g,
                       const float* __restrict__ be) {
    int gid  = blockIdx.x * blockDim.x + threadIdx.x;
    int d    = gid >> 5;
    int lane = gid & 31;
    if (d >= N_NODESC) return;
    const unsigned FULL = 0xffffffffu;
    float Ad0 = d_Ad[2 * d], Ad1 = d_Ad[2 * d + 1];
    int off = d_rowptr[d], end = d_rowptr[d + 1];
    int deg = end - off;

    float ev0 = lrelu(d_As[2 * VN] + Ad0), ev1 = lrelu(d_As[2 * VN + 1] + Ad1);
    float es0 = lrelu(d_As[2 * d]  + Ad0), es1 = lrelu(d_As[2 * d + 1]  + Ad1);

    float ax = 0.f, ay = 0.f, az = 0.f, aw = 0.f;
    const int c = lane * 4;
    float m0, m1, inv0, inv1;

    if (deg <= 32) {
        int s = 0; float l0 = -INFINITY, l1 = -INFINITY;
        if (lane < deg) {
            s  = d_csr[off + lane];
            l0 = lrelu(d_As[2 * s]     + Ad0);
            l1 = lrelu(d_As[2 * s + 1] + Ad1);
        }
        m0 = wmax(fmaxf(l0, fmaxf(ev0, es0)));
        m1 = wmax(fmaxf(l1, fmaxf(ev1, es1)));
        float e0 = (lane < deg) ? __expf(l0 - m0) : 0.f;
        float e1 = (lane < deg) ? __expf(l1 - m1) : 0.f;
        float den0 = wsum(e0) + __expf(ev0 - m0) + __expf(es0 - m0);
        float den1 = wsum(e1) + __expf(ev1 - m1) + __expf(es1 - m1);
        inv0 = 0.5f / (den0 + 1e-16f);
        inv1 = 0.5f / (den1 + 1e-16f);
        float w0 = e0 * inv0, w1 = e1 * inv1;
#pragma unroll 2
        for (int j = 0; j < deg; j++) {
            int   sj  = __shfl_sync(FULL, s,  j);
            float w0j = __shfl_sync(FULL, w0, j);
            float w1j = __shfl_sync(FULL, w1, j);
            gather_edge(sj, w0j, w1j, c, ax, ay, az, aw);
        }
    } else {
        m0 = fmaxf(ev0, es0); m1 = fmaxf(ev1, es1);
        for (int i = off + lane; i < end; i += 32) {
            int s = d_csr[i];
            m0 = fmaxf(m0, lrelu(d_As[2 * s]     + Ad0));
            m1 = fmaxf(m1, lrelu(d_As[2 * s + 1] + Ad1));
        }
        m0 = wmax(m0); m1 = wmax(m1);
        float den0 = 0.f, den1 = 0.f;
        for (int i = off + lane; i < end; i += 32) {
            int s = d_csr[i];
            den0 += __expf(lrelu(d_As[2 * s]     + Ad0) - m0);
            den1 += __expf(lrelu(d_As[2 * s + 1] + Ad1) - m1);
        }
        den0 = wsum(den0) + __expf(ev0 - m0) + __expf(es0 - m0);
        den1 = wsum(den1) + __expf(ev1 - m1) + __expf(es1 - m1);
        inv0 = 0.5f / (den0 + 1e-16f);
        inv1 = 0.5f / (den1 + 1e-16f);
        for (int base = off; base < end; base += 32) {
            int n = min(32, end - base);
            int s = 0; float w0 = 0.f, w1 = 0.f;
            if (lane < n) {
                s  = d_csr[base + lane];
                w0 = __expf(lrelu(d_As[2 * s]     + Ad0) - m0) * inv0;
                w1 = __expf(lrelu(d_As[2 * s + 1] + Ad1) - m1) * inv1;
            }
#pragma unroll 2
            for (int j = 0; j < n; j++) {
                int   sj  = __shfl_sync(FULL, s,  j);
                float w0j = __shfl_sync(FULL, w0, j);
                float w1j = __shfl_sync(FULL, w1, j);
                gather_edge(sj, w0j, w1j, c, ax, ay, az, aw);
            }
        }
    }
    gather_edge(VN, __expf(ev0 - m0) * inv0, __expf(ev1 - m1) * inv1, c, ax, ay, az, aw);
    gather_edge(d,  __expf(es0 - m0) * inv0, __expf(es1 - m1) * inv1, c, ax, ay, az, aw);

    ln_epi(d, lane, ax, ay, az, aw, b, g, be);
}

// ---------------- host launch ----------------
extern "C" void kernel_launch(void* const* d_in, const int* in_sizes, int n_in,
                              void* d_out, int out_size) {
    (void)in_sizes; (void)n_in; (void)out_size;
    const float* X  = (const float*)d_in[0];
    const int*   ei = (const int*)  d_in[1];
    const float* W[3]  = {(const float*)d_in[3],  (const float*)d_in[9],  (const float*)d_in[15]};
    const float* aS[3] = {(const float*)d_in[4],  (const float*)d_in[10], (const float*)d_in[16]};
    const float* aD[3] = {(const float*)d_in[5],  (const float*)d_in[11], (const float*)d_in[17]};
    const float* bb[3] = {(const float*)d_in[6],  (const float*)d_in[12], (const float*)d_in[18]};
    const float* gg[3] = {(const float*)d_in[7],  (const float*)d_in[13], (const float*)d_in[19]};
    const float* bE[3] = {(const float*)d_in[8],  (const float*)d_in[14], (const float*)d_in[20]};
    const float* Wout  = (const float*)d_in[21];
    const float* bout  = (const float*)d_in[22];
    float* out = (float*)d_out;

    int* dCnt; cudaGetSymbolAddress((void**)&dCnt, d_cnt);
    __nv_bfloat16 *dBhi, *dBlo;
    cudaGetSymbolAddress((void**)&dBhi, d_Bhi);
    cudaGetSymbolAddress((void**)&dBlo, d_Blo);

    static cudaStream_t sB = nullptr, sC = nullptr;
    static cudaEvent_t evF = nullptr, evJ = nullptr, evC0 = nullptr, evCJ = nullptr;
    if (!sB) {
        cudaStreamCreateWithFlags(&sB, cudaStreamNonBlocking);
        cudaStreamCreateWithFlags(&sC, cudaStreamNonBlocking);
        cudaEventCreateWithFlags(&evF,  cudaEventDisableTiming);
        cudaEventCreateWithFlags(&evJ,  cudaEventDisableTiming);
        cudaEventCreateWithFlags(&evC0, cudaEventDisableTiming);
        cudaEventCreateWithFlags(&evCJ, cudaEventDisableTiming);
        cudaFuncSetAttribute(wgemm_k,  cudaFuncAttributeMaxDynamicSharedMemorySize, WG_SMEM);
        cudaFuncSetAttribute(wgemmF_k, cudaFuncAttributeMaxDynamicSharedMemorySize, WGF_SMEM);
    }

    // --- fork CSR build onto sC ---
    cudaEventRecord(evC0, 0);
    cudaStreamWaitEvent(sC, evC0, 0);
    cudaMemsetAsync(dCnt, 0, N_NODESC * sizeof(int), sC);
    const int eb = (NEC + 255) / 256;
    hist_k<<<eb, 256, 0, sC>>>(ei);
    scanb_k<<<1, 128, 0, sC>>>();
    rowptr_k<<<NB_SCAN, 512, 0, sC>>>();
    scatter_k<<<eb, 256, 0, sC>>>(ei);
    cudaEventRecord(evCJ, sC);

    // --- main stream ---
    const int wtot = DHIDC * IN_DIMC + 2 * DHIDC * HIDC + OUT_DIMC * HIDC;
    convw_all_k<<<(wtot + 255) / 256, 256>>>(W[0], W[1], W[2], Wout);
    vacc_zero_k<<<1, IN_DIMC>>>();
    vnode_partial_k<<<512, IN_DIMC>>>(X);
    convx0_k<<<(int)(((size_t)NVC * IN_DIMC / 4 + 255) / 256), 256>>>(X);

    const int node_blocks = (N_NODESC * 32 + 255) / 256;

    for (int l = 0; l < 3; l++) {
        int K = (l == 0) ? IN_DIMC : HIDC;
        dim3 grid(DHIDC / 128, MTILES);
        wgemm_k<<<grid, 256, WG_SMEM>>>(dBhi + (size_t)l * DHIDC * IN_DIMC,
                                        dBlo + (size_t)l * DHIDC * IN_DIMC, K,
                                        aS[l], aD[l]);

        cudaEventRecord(evF, 0);
        cudaStreamWaitEvent(sB, evF, 0);
        vn_pre_k<<<1, 1024, 0, sB>>>();
        vn_agg_k<<<VAGG_B, 256, 0, sB>>>();
        vn_fin_k<<<1, HIDC, 0, sB>>>(bb[l], gg[l], bE[l]);

        if (l == 0) cudaStreamWaitEvent(0, evCJ, 0);
        node_k<<<node_blocks, 256>>>(bb[l], gg[l], bE[l]);

        cudaEventRecord(evJ, sB);
        cudaStreamWaitEvent(0, evJ, 0);
    }

    wgemmF_k<<<MTILES, 256, WGF_SMEM>>>(bout, out);
}